// round 4
// baseline (speedup 1.0000x reference)
#include <cuda_runtime.h>
#include <cuda_bf16.h>
#include <math.h>
#include <stdint.h>

#define DIM 384
#define NH 6
#define DH 64
#define BATCH 8
#define SEQ 1024
#define MTOT (BATCH*SEQ)

// ---------------- scratch (device globals; no allocation allowed) ----------
__device__ float g_q [BATCH*NH*SEQ*DH];
__device__ float g_k [BATCH*NH*SEQ*DH];
__device__ float g_v [BATCH*NH*SEQ*DH];
__device__ float g_ao[MTOT*DIM];
__device__ float g_pl[SEQ*SEQ];

__device__ __nv_bfloat16 g_xhi [MTOT*DIM];
__device__ __nv_bfloat16 g_xlo [MTOT*DIM];
__device__ __nv_bfloat16 g_aohi[MTOT*DIM];
__device__ __nv_bfloat16 g_aolo[MTOT*DIM];
__device__ __nv_bfloat16 g_whi [4*DIM*DIM];
__device__ __nv_bfloat16 g_wlo [4*DIM*DIM];

// ---------------- helpers ---------------------------------------------------
static __device__ __forceinline__ uint32_t smem_u32(const void* p) {
    return (uint32_t)__cvta_generic_to_shared(p);
}
static __device__ __forceinline__ void ldsm_x4(uint32_t* r, uint32_t addr) {
    asm volatile("ldmatrix.sync.aligned.m8n8.x4.shared.b16 {%0,%1,%2,%3}, [%4];"
                 : "=r"(r[0]), "=r"(r[1]), "=r"(r[2]), "=r"(r[3]) : "r"(addr));
}
static __device__ __forceinline__ void mma_bf16(float* d, const uint32_t* a,
                                                uint32_t b0, uint32_t b1) {
    asm volatile(
        "mma.sync.aligned.m16n8k16.row.col.f32.bf16.bf16.f32 "
        "{%0,%1,%2,%3}, {%4,%5,%6,%7}, {%8,%9}, {%0,%1,%2,%3};"
        : "+f"(d[0]), "+f"(d[1]), "+f"(d[2]), "+f"(d[3])
        : "r"(a[0]), "r"(a[1]), "r"(a[2]), "r"(a[3]), "r"(b0), "r"(b1));
}
static __device__ __forceinline__ void cp_async16(uint32_t dst, const void* src) {
    asm volatile("cp.async.cg.shared.global [%0], [%1], 16;" :: "r"(dst), "l"(src));
}

// ---------------------------------------------------------------------------
// Positional kernel: g_pl[i][j] = (1-lam) * exp(-dist2(i,j) / (2 sigma^2))
// ---------------------------------------------------------------------------
__global__ void pos_kernel(const float* __restrict__ logit_lambda,
                           const float* __restrict__ log_sigma)
{
    float ls  = log_sigma[0];
    float sig = log1pf(expf(ls)) + 1e-6f;
    float inv = 1.0f / (2.0f * sig * sig);
    float lam = 1.0f / (1.0f + expf(-logit_lambda[0]));
    float oml = 1.0f - lam;

    int i = blockIdx.x;
    float yi = (float)(i >> 5), xi = (float)(i & 31);
    for (int j = threadIdx.x; j < SEQ; j += blockDim.x) {
        float yj = (float)(j >> 5), xj = (float)(j & 31);
        float dy = yi - yj, dx = xi - xj;
        g_pl[i*SEQ + j] = oml * __expf(-(dy*dy + dx*dx) * inv);
    }
}

// ---------------------------------------------------------------------------
// fp32 -> (bf16 hi, bf16 lo) split
// ---------------------------------------------------------------------------
__global__ void convert_split(const float* __restrict__ src,
                              __nv_bfloat16* __restrict__ hi,
                              __nv_bfloat16* __restrict__ lo, int n)
{
    int i = blockIdx.x * 256 + threadIdx.x;
    if (i < n) {
        float v = src[i];
        __nv_bfloat16 h = __float2bfloat16(v);
        hi[i] = h;
        lo[i] = __float2bfloat16(v - __bfloat162float(h));
    }
}

// ---------------------------------------------------------------------------
// mma.sync bf16-split GEMM: D[M,N] = A @ B^T,  A = Ahi+Alo, B = Bhi+Blo
// effective K = 3*384 = 1152 (terms AhiBhi, AhiBlo, AloBhi).
// 128x128 CTA tile, 8 warps (2x4), warp tile 64x32, BK=64, cp.async 2-stage.
// mode 0: write (b,h,n,dh) layout into g_q/g_k/g_v per blockIdx.z
// mode 1: write plain [M, DIM] into proj_out
// ---------------------------------------------------------------------------
#define GEMM_SMEM 65536

__global__ void __launch_bounds__(256) tc_gemm(
    const __nv_bfloat16* __restrict__ Ahi,
    const __nv_bfloat16* __restrict__ Alo,
    const __nv_bfloat16* __restrict__ Bhi_all,
    const __nv_bfloat16* __restrict__ Blo_all,
    float* __restrict__ proj_out,
    int mode)
{
    extern __shared__ char smc[];
    uint32_t sb = smem_u32(smc);
    const uint32_t sA[2] = {sb,           sb + 16384u};
    const uint32_t sB[2] = {sb + 32768u,  sb + 49152u};

    int tid = threadIdx.x, lane = tid & 31, wid = tid >> 5;
    int warpM = wid >> 2, warpN = wid & 3;            // 2 x 4
    int m0 = blockIdx.x * 128, n0 = blockIdx.y * 128, mat = blockIdx.z;

    const __nv_bfloat16* Bhi = Bhi_all + (size_t)mat * DIM * DIM;
    const __nv_bfloat16* Blo = Blo_all + (size_t)mat * DIM * DIM;

    float acc[4][4][4];
    #pragma unroll
    for (int i = 0; i < 4; i++)
        #pragma unroll
        for (int j = 0; j < 4; j++)
            #pragma unroll
            for (int k = 0; k < 4; k++) acc[i][j][k] = 0.f;

    // chunk c (0..17): seg = c/6 selects term, kc = c%6 selects 64-col slice
    auto issue_load = [&](int c) {
        int buf = c & 1;
        int seg = c / 6, kc = c - seg * 6, koff = kc * 64;
        const __nv_bfloat16* Ag = (seg == 2) ? Alo : Ahi;
        const __nv_bfloat16* Bg = (seg == 1) ? Blo : Bhi;
        #pragma unroll
        for (int it = 0; it < 4; it++) {
            int idx = it * 256 + tid;
            int row = idx >> 3, cc = idx & 7;
            uint32_t soff = (uint32_t)(row * 128 + ((cc ^ (row & 7)) << 4));
            cp_async16(sA[buf] + soff, Ag + (size_t)(m0 + row) * DIM + koff + cc * 8);
            cp_async16(sB[buf] + soff, Bg + (size_t)(n0 + row) * DIM + koff + cc * 8);
        }
        asm volatile("cp.async.commit_group;" ::: "memory");
    };

    issue_load(0);

    for (int c = 0; c < 18; c++) {
        if (c + 1 < 18) {
            issue_load(c + 1);
            asm volatile("cp.async.wait_group 1;" ::: "memory");
        } else {
            asm volatile("cp.async.wait_group 0;" ::: "memory");
        }
        __syncthreads();
        int buf = c & 1;
        #pragma unroll
        for (int ks = 0; ks < 4; ks++) {
            uint32_t afrag[4][4];
            #pragma unroll
            for (int mt = 0; mt < 4; mt++) {
                int r = warpM * 64 + mt * 16 + (lane & 15);
                int chunk = ((ks * 2 + (lane >> 4)) ^ (r & 7));
                ldsm_x4(afrag[mt], sA[buf] + (uint32_t)(r * 128 + chunk * 16));
            }
            uint32_t bfrag[2][4];
            #pragma unroll
            for (int bt = 0; bt < 2; bt++) {
                int r = warpN * 32 + bt * 16 + (lane & 15);
                int chunk = ((ks * 2 + (lane >> 4)) ^ (r & 7));
                ldsm_x4(bfrag[bt], sB[buf] + (uint32_t)(r * 128 + chunk * 16));
            }
            #pragma unroll
            for (int mt = 0; mt < 4; mt++)
                #pragma unroll
                for (int nt = 0; nt < 4; nt++) {
                    int bt = nt >> 1, j = nt & 1;
                    mma_bf16(acc[mt][nt], afrag[mt], bfrag[bt][j], bfrag[bt][j + 2]);
                }
        }
        __syncthreads();
    }

    // epilogue: registers -> global (float2 per fragment half)
    int grow = m0 + warpM * 64 + (lane >> 2);
    int gcol = n0 + warpN * 32 + (lane & 3) * 2;
    #pragma unroll
    for (int mt = 0; mt < 4; mt++) {
        #pragma unroll
        for (int nt = 0; nt < 4; nt++) {
            int gm = grow + mt * 16;
            int gn = gcol + nt * 8;
            float2 v0 = make_float2(acc[mt][nt][0], acc[mt][nt][1]);
            float2 v1 = make_float2(acc[mt][nt][2], acc[mt][nt][3]);
            if (mode == 0) {
                float* Y = (mat == 0) ? g_q : (mat == 1) ? g_k : g_v;
                int b = gm >> 10, nrow = gm & 1023;
                int h = gn >> 6,  dd = gn & 63;
                size_t base = ((size_t)(b * NH + h) << 16) + dd;
                *(float2*)(Y + base + ((size_t)nrow       << 6)) = v0;
                *(float2*)(Y + base + ((size_t)(nrow + 8) << 6)) = v1;
            } else {
                *(float2*)(proj_out + (size_t)gm       * DIM + gn) = v0;
                *(float2*)(proj_out + (size_t)(gm + 8) * DIM + gn) = v1;
            }
        }
    }
}

// ---------------------------------------------------------------------------
// Flash-style attention (fp32, unchanged this round)
// ---------------------------------------------------------------------------
#define PSTR 68
#define ATTN_SMEM (4*64*PSTR*4)

__global__ void __launch_bounds__(256) attn_kernel(
    const float* __restrict__ logit_lambda)
{
    extern __shared__ float smf[];
    float* Qs = smf;
    float* Ks = smf +     64*PSTR;
    float* Vs = smf + 2 * 64*PSTR;
    float* Ps = smf + 3 * 64*PSTR;

    int tid = threadIdx.x;
    int bh = blockIdx.y;
    int q0 = blockIdx.x * 64;
    int b_ = bh / NH, head = bh % NH;

    const float* qb = g_q + ((size_t)bh << 16);
    const float* kb = g_k + ((size_t)bh << 16);
    const float* vb = g_v + ((size_t)bh << 16);

    float lam   = 1.0f / (1.0f + __expf(-logit_lambda[0]));
    float scale = lam * 0.125f;

    #pragma unroll
    for (int u = 0; u < 4; u++) {
        int idx = u*256 + tid;
        int row = idx >> 4, c4 = (idx & 15) << 2;
        *(float4*)&Qs[row*PSTR + c4] = *(const float4*)&qb[((q0+row) << 6) + c4];
    }

    int rr = tid >> 3;
    int sg = tid & 7;

    float m0 = -1e30f, m1 = -1e30f, l0 = 0.f, l1 = 0.f;
    float o0[8], o1[8];
    #pragma unroll
    for (int c = 0; c < 8; c++) { o0[c] = 0.f; o1[c] = 0.f; }

    for (int kt = 0; kt < SEQ/64; kt++) {
        __syncthreads();
        int k0 = kt * 64;
        #pragma unroll
        for (int u = 0; u < 4; u++) {
            int idx = u*256 + tid;
            int row = idx >> 4, c4 = (idx & 15) << 2;
            *(float4*)&Ks[row*PSTR + c4] = *(const float4*)&kb[((k0+row) << 6) + c4];
            *(float4*)&Vs[row*PSTR + c4] = *(const float4*)&vb[((k0+row) << 6) + c4];
            *(float4*)&Ps[row*PSTR + c4] = *(const float4*)&g_pl[(size_t)(q0+row)*SEQ + k0 + c4];
        }
        __syncthreads();

        float s0[8], s1[8];
        #pragma unroll
        for (int t = 0; t < 8; t++) { s0[t] = 0.f; s1[t] = 0.f; }
        #pragma unroll
        for (int d0 = 0; d0 < DH; d0 += 4) {
            float4 qa = *(const float4*)&Qs[rr*PSTR + d0];
            float4 qc = *(const float4*)&Qs[(rr+32)*PSTR + d0];
            #pragma unroll
            for (int t = 0; t < 8; t++) {
                float4 kv = *(const float4*)&Ks[(sg + 8*t)*PSTR + d0];
                s0[t] += qa.x*kv.x + qa.y*kv.y + qa.z*kv.z + qa.w*kv.w;
                s1[t] += qc.x*kv.x + qc.y*kv.y + qc.z*kv.z + qc.w*kv.w;
            }
        }
        float tm0 = -1e30f, tm1 = -1e30f;
        #pragma unroll
        for (int t = 0; t < 8; t++) {
            int col = sg + 8*t;
            s0[t] = scale*s0[t] + Ps[rr*PSTR + col];
            s1[t] = scale*s1[t] + Ps[(rr+32)*PSTR + col];
            tm0 = fmaxf(tm0, s0[t]);
            tm1 = fmaxf(tm1, s1[t]);
        }
        #pragma unroll
        for (int off = 1; off < 8; off <<= 1) {
            tm0 = fmaxf(tm0, __shfl_xor_sync(0xffffffffu, tm0, off));
            tm1 = fmaxf(tm1, __shfl_xor_sync(0xffffffffu, tm1, off));
        }
        float nm0 = fmaxf(m0, tm0), nm1 = fmaxf(m1, tm1);
        float r0 = __expf(m0 - nm0), r1 = __expf(m1 - nm1);
        float ts0 = 0.f, ts1 = 0.f;
        #pragma unroll
        for (int t = 0; t < 8; t++) {
            float p0 = __expf(s0[t] - nm0);
            float p1 = __expf(s1[t] - nm1);
            ts0 += p0; ts1 += p1;
            int col = sg + 8*t;
            Ps[rr*PSTR + col]      = p0;
            Ps[(rr+32)*PSTR + col] = p1;
        }
        #pragma unroll
        for (int off = 1; off < 8; off <<= 1) {
            ts0 += __shfl_xor_sync(0xffffffffu, ts0, off);
            ts1 += __shfl_xor_sync(0xffffffffu, ts1, off);
        }
        l0 = l0*r0 + ts0;  l1 = l1*r1 + ts1;
        m0 = nm0;          m1 = nm1;
        #pragma unroll
        for (int c = 0; c < 8; c++) { o0[c] *= r0; o1[c] *= r1; }
        __syncthreads();

        #pragma unroll 4
        for (int jj = 0; jj < 64; jj++) {
            float p0 = Ps[rr*PSTR + jj];
            float p1 = Ps[(rr+32)*PSTR + jj];
            float4 va = *(const float4*)&Vs[jj*PSTR + sg*4];
            float4 vc = *(const float4*)&Vs[jj*PSTR + sg*4 + 32];
            o0[0] += p0*va.x; o0[1] += p0*va.y; o0[2] += p0*va.z; o0[3] += p0*va.w;
            o0[4] += p0*vc.x; o0[5] += p0*vc.y; o0[6] += p0*vc.z; o0[7] += p0*vc.w;
            o1[0] += p1*va.x; o1[1] += p1*va.y; o1[2] += p1*va.z; o1[3] += p1*va.w;
            o1[4] += p1*vc.x; o1[5] += p1*vc.y; o1[6] += p1*vc.z; o1[7] += p1*vc.w;
        }
    }

    float i0 = 1.0f / l0, i1 = 1.0f / l1;
    size_t base0 = (size_t)(b_*SEQ + q0 + rr     )*DIM + head*DH;
    size_t base1 = (size_t)(b_*SEQ + q0 + rr + 32)*DIM + head*DH;
    *(float4*)&g_ao[base0 + sg*4]      = make_float4(o0[0]*i0, o0[1]*i0, o0[2]*i0, o0[3]*i0);
    *(float4*)&g_ao[base0 + sg*4 + 32] = make_float4(o0[4]*i0, o0[5]*i0, o0[6]*i0, o0[7]*i0);
    *(float4*)&g_ao[base1 + sg*4]      = make_float4(o1[0]*i1, o1[1]*i1, o1[2]*i1, o1[3]*i1);
    *(float4*)&g_ao[base1 + sg*4 + 32] = make_float4(o1[4]*i1, o1[5]*i1, o1[6]*i1, o1[7]*i1);
}

// ---------------------------------------------------------------------------
extern "C" void kernel_launch(void* const* d_in, const int* in_sizes, int n_in,
                              void* d_out, int out_size)
{
    const float* x  = (const float*)d_in[0];
    const float* Wq = (const float*)d_in[1];
    const float* Wk = (const float*)d_in[2];
    const float* Wv = (const float*)d_in[3];
    const float* Wp = (const float*)d_in[4];
    const float* ll = (const float*)d_in[5];
    const float* ls = (const float*)d_in[6];
    float* out = (float*)d_out;

    cudaFuncSetAttribute(attn_kernel,
                         cudaFuncAttributeMaxDynamicSharedMemorySize, ATTN_SMEM);
    cudaFuncSetAttribute(tc_gemm,
                         cudaFuncAttributeMaxDynamicSharedMemorySize, GEMM_SMEM);

    __nv_bfloat16 *xhi, *xlo, *aohi, *aolo, *whi, *wlo;
    cudaGetSymbolAddress((void**)&xhi,  g_xhi);
    cudaGetSymbolAddress((void**)&xlo,  g_xlo);
    cudaGetSymbolAddress((void**)&aohi, g_aohi);
    cudaGetSymbolAddress((void**)&aolo, g_aolo);
    cudaGetSymbolAddress((void**)&whi,  g_whi);
    cudaGetSymbolAddress((void**)&wlo,  g_wlo);
    float* ao;
    cudaGetSymbolAddress((void**)&ao, g_ao);

    pos_kernel<<<SEQ, 256>>>(ll, ls);

    convert_split<<<(MTOT*DIM + 255)/256, 256>>>(x, xhi, xlo, MTOT*DIM);
    convert_split<<<(DIM*DIM + 255)/256, 256>>>(Wq, whi + 0*DIM*DIM, wlo + 0*DIM*DIM, DIM*DIM);
    convert_split<<<(DIM*DIM + 255)/256, 256>>>(Wk, whi + 1*DIM*DIM, wlo + 1*DIM*DIM, DIM*DIM);
    convert_split<<<(DIM*DIM + 255)/256, 256>>>(Wv, whi + 2*DIM*DIM, wlo + 2*DIM*DIM, DIM*DIM);
    convert_split<<<(DIM*DIM + 255)/256, 256>>>(Wp, whi + 3*DIM*DIM, wlo + 3*DIM*DIM, DIM*DIM);

    tc_gemm<<<dim3(64, 3, 3), 256, GEMM_SMEM>>>(xhi, xlo, whi, wlo, nullptr, 0);

    attn_kernel<<<dim3(SEQ/64, BATCH*NH), 256, ATTN_SMEM>>>(ll);

    convert_split<<<(MTOT*DIM + 255)/256, 256>>>(ao, aohi, aolo, MTOT*DIM);
    tc_gemm<<<dim3(64, 3, 1), 256, GEMM_SMEM>>>(aohi, aolo,
                                                whi + 3*DIM*DIM, wlo + 3*DIM*DIM,
                                                out, 1);
}

// round 5
// speedup vs baseline: 1.0008x; 1.0008x over previous
#include <cuda_runtime.h>
#include <cuda_bf16.h>
#include <math.h>
#include <stdint.h>

#define DIM 384
#define NH 6
#define DH 64
#define BATCH 8
#define SEQ 1024
#define MTOT (BATCH*SEQ)

// ---------------- scratch (device globals; no allocation allowed) ----------
__device__ float g_q [BATCH*NH*SEQ*DH];
__device__ float g_k [BATCH*NH*SEQ*DH];
__device__ float g_v [BATCH*NH*SEQ*DH];
__device__ float g_ao[MTOT*DIM];
__device__ float g_pl[SEQ*SEQ];

__device__ __nv_bfloat16 g_xhi [MTOT*DIM];
__device__ __nv_bfloat16 g_xlo [MTOT*DIM];
__device__ __nv_bfloat16 g_aohi[MTOT*DIM];
__device__ __nv_bfloat16 g_aolo[MTOT*DIM];
__device__ __nv_bfloat16 g_whi [4*DIM*DIM];
__device__ __nv_bfloat16 g_wlo [4*DIM*DIM];

// ---------------- helpers ---------------------------------------------------
static __device__ __forceinline__ uint32_t smem_u32(const void* p) {
    return (uint32_t)__cvta_generic_to_shared(p);
}
static __device__ __forceinline__ void ldsm_x4(uint32_t* r, uint32_t addr) {
    asm volatile("ldmatrix.sync.aligned.m8n8.x4.shared.b16 {%0,%1,%2,%3}, [%4];"
                 : "=r"(r[0]), "=r"(r[1]), "=r"(r[2]), "=r"(r[3]) : "r"(addr));
}
static __device__ __forceinline__ void mma_bf16(float* d, const uint32_t* a,
                                                uint32_t b0, uint32_t b1) {
    asm volatile(
        "mma.sync.aligned.m16n8k16.row.col.f32.bf16.bf16.f32 "
        "{%0,%1,%2,%3}, {%4,%5,%6,%7}, {%8,%9}, {%0,%1,%2,%3};"
        : "+f"(d[0]), "+f"(d[1]), "+f"(d[2]), "+f"(d[3])
        : "r"(a[0]), "r"(a[1]), "r"(a[2]), "r"(a[3]), "r"(b0), "r"(b1));
}
static __device__ __forceinline__ void cp_async16(uint32_t dst, const void* src) {
    asm volatile("cp.async.cg.shared.global [%0], [%1], 16;" :: "r"(dst), "l"(src));
}

// ---------------------------------------------------------------------------
// Positional kernel: g_pl[i][j] = (1-lam) * exp(-dist2(i,j) / (2 sigma^2))
// ---------------------------------------------------------------------------
__global__ void pos_kernel(const float* __restrict__ logit_lambda,
                           const float* __restrict__ log_sigma)
{
    float ls  = log_sigma[0];
    float sig = log1pf(expf(ls)) + 1e-6f;
    float inv = 1.0f / (2.0f * sig * sig);
    float lam = 1.0f / (1.0f + expf(-logit_lambda[0]));
    float oml = 1.0f - lam;

    int i = blockIdx.x;
    float yi = (float)(i >> 5), xi = (float)(i & 31);
    for (int j = threadIdx.x; j < SEQ; j += blockDim.x) {
        float yj = (float)(j >> 5), xj = (float)(j & 31);
        float dy = yi - yj, dx = xi - xj;
        g_pl[i*SEQ + j] = oml * __expf(-(dy*dy + dx*dx) * inv);
    }
}

// ---------------------------------------------------------------------------
// fp32 -> (bf16 hi, bf16 lo) split
// ---------------------------------------------------------------------------
__global__ void convert_split(const float* __restrict__ src,
                              __nv_bfloat16* __restrict__ hi,
                              __nv_bfloat16* __restrict__ lo, int n)
{
    int i = blockIdx.x * 256 + threadIdx.x;
    if (i < n) {
        float v = src[i];
        __nv_bfloat16 h = __float2bfloat16(v);
        hi[i] = h;
        lo[i] = __float2bfloat16(v - __bfloat162float(h));
    }
}

// ---------------------------------------------------------------------------
// mma.sync bf16-split GEMM: D[M,N] = A @ B^T,  A = Ahi+Alo, B = Bhi+Blo
// effective K = 3*384 = 1152 (terms AhiBhi, AhiBlo, AloBhi).
// 128x128 CTA tile, 8 warps (2x4), warp tile 64x32, BK=64, cp.async 2-stage.
// mode 0: write (b,h,n,dh) layout into g_q/g_k/g_v per blockIdx.z
// mode 1: write plain [M, DIM] into proj_out
// ---------------------------------------------------------------------------
#define GEMM_SMEM 65536

__global__ void __launch_bounds__(256) tc_gemm(
    const __nv_bfloat16* __restrict__ Ahi,
    const __nv_bfloat16* __restrict__ Alo,
    const __nv_bfloat16* __restrict__ Bhi_all,
    const __nv_bfloat16* __restrict__ Blo_all,
    float* __restrict__ proj_out,
    int mode)
{
    extern __shared__ char smc[];
    uint32_t sb = smem_u32(smc);
    const uint32_t sA[2] = {sb,           sb + 16384u};
    const uint32_t sB[2] = {sb + 32768u,  sb + 49152u};

    int tid = threadIdx.x, lane = tid & 31, wid = tid >> 5;
    int warpM = wid >> 2, warpN = wid & 3;            // 2 x 4
    int m0 = blockIdx.x * 128, n0 = blockIdx.y * 128, mat = blockIdx.z;

    const __nv_bfloat16* Bhi = Bhi_all + (size_t)mat * DIM * DIM;
    const __nv_bfloat16* Blo = Blo_all + (size_t)mat * DIM * DIM;

    float acc[4][4][4];
    #pragma unroll
    for (int i = 0; i < 4; i++)
        #pragma unroll
        for (int j = 0; j < 4; j++)
            #pragma unroll
            for (int k = 0; k < 4; k++) acc[i][j][k] = 0.f;

    // chunk c (0..17): seg = c/6 selects term, kc = c%6 selects 64-col slice
    auto issue_load = [&](int c) {
        int buf = c & 1;
        int seg = c / 6, kc = c - seg * 6, koff = kc * 64;
        const __nv_bfloat16* Ag = (seg == 2) ? Alo : Ahi;
        const __nv_bfloat16* Bg = (seg == 1) ? Blo : Bhi;
        #pragma unroll
        for (int it = 0; it < 4; it++) {
            int idx = it * 256 + tid;
            int row = idx >> 3, cc = idx & 7;
            uint32_t soff = (uint32_t)(row * 128 + ((cc ^ (row & 7)) << 4));
            cp_async16(sA[buf] + soff, Ag + (size_t)(m0 + row) * DIM + koff + cc * 8);
            cp_async16(sB[buf] + soff, Bg + (size_t)(n0 + row) * DIM + koff + cc * 8);
        }
        asm volatile("cp.async.commit_group;" ::: "memory");
    };

    issue_load(0);

    for (int c = 0; c < 18; c++) {
        if (c + 1 < 18) {
            issue_load(c + 1);
            asm volatile("cp.async.wait_group 1;" ::: "memory");
        } else {
            asm volatile("cp.async.wait_group 0;" ::: "memory");
        }
        __syncthreads();
        int buf = c & 1;
        #pragma unroll
        for (int ks = 0; ks < 4; ks++) {
            uint32_t afrag[4][4];
            #pragma unroll
            for (int mt = 0; mt < 4; mt++) {
                int r = warpM * 64 + mt * 16 + (lane & 15);
                int chunk = ((ks * 2 + (lane >> 4)) ^ (r & 7));
                ldsm_x4(afrag[mt], sA[buf] + (uint32_t)(r * 128 + chunk * 16));
            }
            uint32_t bfrag[2][4];
            #pragma unroll
            for (int bt = 0; bt < 2; bt++) {
                int r = warpN * 32 + bt * 16 + (lane & 15);
                int chunk = ((ks * 2 + (lane >> 4)) ^ (r & 7));
                ldsm_x4(bfrag[bt], sB[buf] + (uint32_t)(r * 128 + chunk * 16));
            }
            #pragma unroll
            for (int mt = 0; mt < 4; mt++)
                #pragma unroll
                for (int nt = 0; nt < 4; nt++) {
                    int bt = nt >> 1, j = nt & 1;
                    mma_bf16(acc[mt][nt], afrag[mt], bfrag[bt][j], bfrag[bt][j + 2]);
                }
        }
        __syncthreads();
    }

    // epilogue: registers -> global (float2 per fragment half)
    int grow = m0 + warpM * 64 + (lane >> 2);
    int gcol = n0 + warpN * 32 + (lane & 3) * 2;
    #pragma unroll
    for (int mt = 0; mt < 4; mt++) {
        #pragma unroll
        for (int nt = 0; nt < 4; nt++) {
            int gm = grow + mt * 16;
            int gn = gcol + nt * 8;
            float2 v0 = make_float2(acc[mt][nt][0], acc[mt][nt][1]);
            float2 v1 = make_float2(acc[mt][nt][2], acc[mt][nt][3]);
            if (mode == 0) {
                float* Y = (mat == 0) ? g_q : (mat == 1) ? g_k : g_v;
                int b = gm >> 10, nrow = gm & 1023;
                int h = gn >> 6,  dd = gn & 63;
                size_t base = ((size_t)(b * NH + h) << 16) + dd;
                *(float2*)(Y + base + ((size_t)nrow       << 6)) = v0;
                *(float2*)(Y + base + ((size_t)(nrow + 8) << 6)) = v1;
            } else {
                *(float2*)(proj_out + (size_t)gm       * DIM + gn) = v0;
                *(float2*)(proj_out + (size_t)(gm + 8) * DIM + gn) = v1;
            }
        }
    }
}

// ---------------------------------------------------------------------------
// Flash-style attention (fp32, unchanged this round)
// ---------------------------------------------------------------------------
#define PSTR 68
#define ATTN_SMEM (4*64*PSTR*4)

__global__ void __launch_bounds__(256) attn_kernel(
    const float* __restrict__ logit_lambda)
{
    extern __shared__ float smf[];
    float* Qs = smf;
    float* Ks = smf +     64*PSTR;
    float* Vs = smf + 2 * 64*PSTR;
    float* Ps = smf + 3 * 64*PSTR;

    int tid = threadIdx.x;
    int bh = blockIdx.y;
    int q0 = blockIdx.x * 64;
    int b_ = bh / NH, head = bh % NH;

    const float* qb = g_q + ((size_t)bh << 16);
    const float* kb = g_k + ((size_t)bh << 16);
    const float* vb = g_v + ((size_t)bh << 16);

    float lam   = 1.0f / (1.0f + __expf(-logit_lambda[0]));
    float scale = lam * 0.125f;

    #pragma unroll
    for (int u = 0; u < 4; u++) {
        int idx = u*256 + tid;
        int row = idx >> 4, c4 = (idx & 15) << 2;
        *(float4*)&Qs[row*PSTR + c4] = *(const float4*)&qb[((q0+row) << 6) + c4];
    }

    int rr = tid >> 3;
    int sg = tid & 7;

    float m0 = -1e30f, m1 = -1e30f, l0 = 0.f, l1 = 0.f;
    float o0[8], o1[8];
    #pragma unroll
    for (int c = 0; c < 8; c++) { o0[c] = 0.f; o1[c] = 0.f; }

    for (int kt = 0; kt < SEQ/64; kt++) {
        __syncthreads();
        int k0 = kt * 64;
        #pragma unroll
        for (int u = 0; u < 4; u++) {
            int idx = u*256 + tid;
            int row = idx >> 4, c4 = (idx & 15) << 2;
            *(float4*)&Ks[row*PSTR + c4] = *(const float4*)&kb[((k0+row) << 6) + c4];
            *(float4*)&Vs[row*PSTR + c4] = *(const float4*)&vb[((k0+row) << 6) + c4];
            *(float4*)&Ps[row*PSTR + c4] = *(const float4*)&g_pl[(size_t)(q0+row)*SEQ + k0 + c4];
        }
        __syncthreads();

        float s0[8], s1[8];
        #pragma unroll
        for (int t = 0; t < 8; t++) { s0[t] = 0.f; s1[t] = 0.f; }
        #pragma unroll
        for (int d0 = 0; d0 < DH; d0 += 4) {
            float4 qa = *(const float4*)&Qs[rr*PSTR + d0];
            float4 qc = *(const float4*)&Qs[(rr+32)*PSTR + d0];
            #pragma unroll
            for (int t = 0; t < 8; t++) {
                float4 kv = *(const float4*)&Ks[(sg + 8*t)*PSTR + d0];
                s0[t] += qa.x*kv.x + qa.y*kv.y + qa.z*kv.z + qa.w*kv.w;
                s1[t] += qc.x*kv.x + qc.y*kv.y + qc.z*kv.z + qc.w*kv.w;
            }
        }
        float tm0 = -1e30f, tm1 = -1e30f;
        #pragma unroll
        for (int t = 0; t < 8; t++) {
            int col = sg + 8*t;
            s0[t] = scale*s0[t] + Ps[rr*PSTR + col];
            s1[t] = scale*s1[t] + Ps[(rr+32)*PSTR + col];
            tm0 = fmaxf(tm0, s0[t]);
            tm1 = fmaxf(tm1, s1[t]);
        }
        #pragma unroll
        for (int off = 1; off < 8; off <<= 1) {
            tm0 = fmaxf(tm0, __shfl_xor_sync(0xffffffffu, tm0, off));
            tm1 = fmaxf(tm1, __shfl_xor_sync(0xffffffffu, tm1, off));
        }
        float nm0 = fmaxf(m0, tm0), nm1 = fmaxf(m1, tm1);
        float r0 = __expf(m0 - nm0), r1 = __expf(m1 - nm1);
        float ts0 = 0.f, ts1 = 0.f;
        #pragma unroll
        for (int t = 0; t < 8; t++) {
            float p0 = __expf(s0[t] - nm0);
            float p1 = __expf(s1[t] - nm1);
            ts0 += p0; ts1 += p1;
            int col = sg + 8*t;
            Ps[rr*PSTR + col]      = p0;
            Ps[(rr+32)*PSTR + col] = p1;
        }
        #pragma unroll
        for (int off = 1; off < 8; off <<= 1) {
            ts0 += __shfl_xor_sync(0xffffffffu, ts0, off);
            ts1 += __shfl_xor_sync(0xffffffffu, ts1, off);
        }
        l0 = l0*r0 + ts0;  l1 = l1*r1 + ts1;
        m0 = nm0;          m1 = nm1;
        #pragma unroll
        for (int c = 0; c < 8; c++) { o0[c] *= r0; o1[c] *= r1; }
        __syncthreads();

        #pragma unroll 4
        for (int jj = 0; jj < 64; jj++) {
            float p0 = Ps[rr*PSTR + jj];
            float p1 = Ps[(rr+32)*PSTR + jj];
            float4 va = *(const float4*)&Vs[jj*PSTR + sg*4];
            float4 vc = *(const float4*)&Vs[jj*PSTR + sg*4 + 32];
            o0[0] += p0*va.x; o0[1] += p0*va.y; o0[2] += p0*va.z; o0[3] += p0*va.w;
            o0[4] += p0*vc.x; o0[5] += p0*vc.y; o0[6] += p0*vc.z; o0[7] += p0*vc.w;
            o1[0] += p1*va.x; o1[1] += p1*va.y; o1[2] += p1*va.z; o1[3] += p1*va.w;
            o1[4] += p1*vc.x; o1[5] += p1*vc.y; o1[6] += p1*vc.z; o1[7] += p1*vc.w;
        }
    }

    float i0 = 1.0f / l0, i1 = 1.0f / l1;
    size_t base0 = (size_t)(b_*SEQ + q0 + rr     )*DIM + head*DH;
    size_t base1 = (size_t)(b_*SEQ + q0 + rr + 32)*DIM + head*DH;
    *(float4*)&g_ao[base0 + sg*4]      = make_float4(o0[0]*i0, o0[1]*i0, o0[2]*i0, o0[3]*i0);
    *(float4*)&g_ao[base0 + sg*4 + 32] = make_float4(o0[4]*i0, o0[5]*i0, o0[6]*i0, o0[7]*i0);
    *(float4*)&g_ao[base1 + sg*4]      = make_float4(o1[0]*i1, o1[1]*i1, o1[2]*i1, o1[3]*i1);
    *(float4*)&g_ao[base1 + sg*4 + 32] = make_float4(o1[4]*i1, o1[5]*i1, o1[6]*i1, o1[7]*i1);
}

// ---------------------------------------------------------------------------
extern "C" void kernel_launch(void* const* d_in, const int* in_sizes, int n_in,
                              void* d_out, int out_size)
{
    const float* x  = (const float*)d_in[0];
    const float* Wq = (const float*)d_in[1];
    const float* Wk = (const float*)d_in[2];
    const float* Wv = (const float*)d_in[3];
    const float* Wp = (const float*)d_in[4];
    const float* ll = (const float*)d_in[5];
    const float* ls = (const float*)d_in[6];
    float* out = (float*)d_out;

    cudaFuncSetAttribute(attn_kernel,
                         cudaFuncAttributeMaxDynamicSharedMemorySize, ATTN_SMEM);
    cudaFuncSetAttribute(tc_gemm,
                         cudaFuncAttributeMaxDynamicSharedMemorySize, GEMM_SMEM);

    __nv_bfloat16 *xhi, *xlo, *aohi, *aolo, *whi, *wlo;
    cudaGetSymbolAddress((void**)&xhi,  g_xhi);
    cudaGetSymbolAddress((void**)&xlo,  g_xlo);
    cudaGetSymbolAddress((void**)&aohi, g_aohi);
    cudaGetSymbolAddress((void**)&aolo, g_aolo);
    cudaGetSymbolAddress((void**)&whi,  g_whi);
    cudaGetSymbolAddress((void**)&wlo,  g_wlo);
    float* ao;
    cudaGetSymbolAddress((void**)&ao, g_ao);

    pos_kernel<<<SEQ, 256>>>(ll, ls);

    convert_split<<<(MTOT*DIM + 255)/256, 256>>>(x, xhi, xlo, MTOT*DIM);
    convert_split<<<(DIM*DIM + 255)/256, 256>>>(Wq, whi + 0*DIM*DIM, wlo + 0*DIM*DIM, DIM*DIM);
    convert_split<<<(DIM*DIM + 255)/256, 256>>>(Wk, whi + 1*DIM*DIM, wlo + 1*DIM*DIM, DIM*DIM);
    convert_split<<<(DIM*DIM + 255)/256, 256>>>(Wv, whi + 2*DIM*DIM, wlo + 2*DIM*DIM, DIM*DIM);
    convert_split<<<(DIM*DIM + 255)/256, 256>>>(Wp, whi + 3*DIM*DIM, wlo + 3*DIM*DIM, DIM*DIM);

    tc_gemm<<<dim3(64, 3, 3), 256, GEMM_SMEM>>>(xhi, xlo, whi, wlo, nullptr, 0);

    attn_kernel<<<dim3(SEQ/64, BATCH*NH), 256, ATTN_SMEM>>>(ll);

    convert_split<<<(MTOT*DIM + 255)/256, 256>>>(ao, aohi, aolo, MTOT*DIM);
    tc_gemm<<<dim3(64, 3, 1), 256, GEMM_SMEM>>>(aohi, aolo,
                                                whi + 3*DIM*DIM, wlo + 3*DIM*DIM,
                                                out, 1);
}

// round 6
// speedup vs baseline: 2.2744x; 2.2727x over previous
#include <cuda_runtime.h>
#include <cuda_bf16.h>
#include <math.h>
#include <stdint.h>

#define DIM 384
#define NH 6
#define DH 64
#define BATCH 8
#define SEQ 1024
#define MTOT (BATCH*SEQ)

// ---------------- scratch (device globals; no allocation allowed) ----------
__device__ float g_pl[SEQ*SEQ];

__device__ __nv_bfloat16 g_qhi[BATCH*NH*SEQ*DH];
__device__ __nv_bfloat16 g_qlo[BATCH*NH*SEQ*DH];
__device__ __nv_bfloat16 g_khi[BATCH*NH*SEQ*DH];
__device__ __nv_bfloat16 g_klo[BATCH*NH*SEQ*DH];
__device__ __nv_bfloat16 g_vhi[BATCH*NH*SEQ*DH];
__device__ __nv_bfloat16 g_vlo[BATCH*NH*SEQ*DH];

__device__ __nv_bfloat16 g_xhi [MTOT*DIM];
__device__ __nv_bfloat16 g_xlo [MTOT*DIM];
__device__ __nv_bfloat16 g_aohi[MTOT*DIM];
__device__ __nv_bfloat16 g_aolo[MTOT*DIM];
__device__ __nv_bfloat16 g_whi [4*DIM*DIM];
__device__ __nv_bfloat16 g_wlo [4*DIM*DIM];

// ---------------- helpers ---------------------------------------------------
static __device__ __forceinline__ uint32_t smem_u32(const void* p) {
    return (uint32_t)__cvta_generic_to_shared(p);
}
static __device__ __forceinline__ void ldsm_x4(uint32_t* r, uint32_t addr) {
    asm volatile("ldmatrix.sync.aligned.m8n8.x4.shared.b16 {%0,%1,%2,%3}, [%4];"
                 : "=r"(r[0]), "=r"(r[1]), "=r"(r[2]), "=r"(r[3]) : "r"(addr));
}
static __device__ __forceinline__ void ldsm_x4_t(uint32_t* r, uint32_t addr) {
    asm volatile("ldmatrix.sync.aligned.m8n8.x4.trans.shared.b16 {%0,%1,%2,%3}, [%4];"
                 : "=r"(r[0]), "=r"(r[1]), "=r"(r[2]), "=r"(r[3]) : "r"(addr));
}
static __device__ __forceinline__ void mma_bf16(float* d, const uint32_t* a,
                                                uint32_t b0, uint32_t b1) {
    asm volatile(
        "mma.sync.aligned.m16n8k16.row.col.f32.bf16.bf16.f32 "
        "{%0,%1,%2,%3}, {%4,%5,%6,%7}, {%8,%9}, {%0,%1,%2,%3};"
        : "+f"(d[0]), "+f"(d[1]), "+f"(d[2]), "+f"(d[3])
        : "r"(a[0]), "r"(a[1]), "r"(a[2]), "r"(a[3]), "r"(b0), "r"(b1));
}
static __device__ __forceinline__ void cp_async16(uint32_t dst, const void* src) {
    asm volatile("cp.async.cg.shared.global [%0], [%1], 16;" :: "r"(dst), "l"(src));
}
// pack (lo=a, hi=b) into bf16x2; little-endian: low half = element at col 2t.
static __device__ __forceinline__ uint32_t pack_bf16(float a, float b) {
    uint32_t r;
    asm("cvt.rn.bf16x2.f32 %0, %1, %2;" : "=r"(r) : "f"(b), "f"(a));
    return r;
}
static __device__ __forceinline__ void split_pair(float a, float b,
                                                  uint32_t& hi, uint32_t& lo) {
    hi = pack_bf16(a, b);
    float fa = __uint_as_float(hi << 16);
    float fb = __uint_as_float(hi & 0xffff0000u);
    lo = pack_bf16(a - fa, b - fb);
}

// ---------------------------------------------------------------------------
// Positional kernel: g_pl[i][j] = (1-lam) * exp(-dist2(i,j) / (2 sigma^2))
// ---------------------------------------------------------------------------
__global__ void pos_kernel(const float* __restrict__ logit_lambda,
                           const float* __restrict__ log_sigma)
{
    float ls  = log_sigma[0];
    float sig = log1pf(expf(ls)) + 1e-6f;
    float inv = 1.0f / (2.0f * sig * sig);
    float lam = 1.0f / (1.0f + expf(-logit_lambda[0]));
    float oml = 1.0f - lam;

    int i = blockIdx.x;
    float yi = (float)(i >> 5), xi = (float)(i & 31);
    for (int j = threadIdx.x; j < SEQ; j += blockDim.x) {
        float yj = (float)(j >> 5), xj = (float)(j & 31);
        float dy = yi - yj, dx = xi - xj;
        g_pl[i*SEQ + j] = oml * __expf(-(dy*dy + dx*dx) * inv);
    }
}

// ---------------------------------------------------------------------------
// fp32 -> (bf16 hi, bf16 lo) split
// ---------------------------------------------------------------------------
__global__ void convert_split(const float* __restrict__ src,
                              __nv_bfloat16* __restrict__ hi,
                              __nv_bfloat16* __restrict__ lo, int n)
{
    int i = blockIdx.x * 256 + threadIdx.x;
    if (i < n) {
        float v = src[i];
        __nv_bfloat16 h = __float2bfloat16(v);
        hi[i] = h;
        lo[i] = __float2bfloat16(v - __bfloat162float(h));
    }
}

// ---------------------------------------------------------------------------
// mma.sync bf16-split GEMM: D[M,N] = A @ B^T,  A = Ahi+Alo, B = Bhi+Blo
// mode 0: split D -> (g_q/g_k/g_v)(hi,lo) in (b,h,n,dh) bf16 layout
// mode 1: write fp32 [M, DIM] into proj_out
// ---------------------------------------------------------------------------
#define GEMM_SMEM 65536

__global__ void __launch_bounds__(256) tc_gemm(
    const __nv_bfloat16* __restrict__ Ahi,
    const __nv_bfloat16* __restrict__ Alo,
    const __nv_bfloat16* __restrict__ Bhi_all,
    const __nv_bfloat16* __restrict__ Blo_all,
    float* __restrict__ proj_out,
    int mode)
{
    extern __shared__ char smc[];
    uint32_t sb = smem_u32(smc);
    const uint32_t sA[2] = {sb,           sb + 16384u};
    const uint32_t sB[2] = {sb + 32768u,  sb + 49152u};

    int tid = threadIdx.x, lane = tid & 31, wid = tid >> 5;
    int warpM = wid >> 2, warpN = wid & 3;            // 2 x 4
    int m0 = blockIdx.x * 128, n0 = blockIdx.y * 128, mat = blockIdx.z;

    const __nv_bfloat16* Bhi = Bhi_all + (size_t)mat * DIM * DIM;
    const __nv_bfloat16* Blo = Blo_all + (size_t)mat * DIM * DIM;

    float acc[4][4][4];
    #pragma unroll
    for (int i = 0; i < 4; i++)
        #pragma unroll
        for (int j = 0; j < 4; j++)
            #pragma unroll
            for (int k = 0; k < 4; k++) acc[i][j][k] = 0.f;

    auto issue_load = [&](int c) {
        int buf = c & 1;
        int seg = c / 6, kc = c - seg * 6, koff = kc * 64;
        const __nv_bfloat16* Ag = (seg == 2) ? Alo : Ahi;
        const __nv_bfloat16* Bg = (seg == 1) ? Blo : Bhi;
        #pragma unroll
        for (int it = 0; it < 4; it++) {
            int idx = it * 256 + tid;
            int row = idx >> 3, cc = idx & 7;
            uint32_t soff = (uint32_t)(row * 128 + ((cc ^ (row & 7)) << 4));
            cp_async16(sA[buf] + soff, Ag + (size_t)(m0 + row) * DIM + koff + cc * 8);
            cp_async16(sB[buf] + soff, Bg + (size_t)(n0 + row) * DIM + koff + cc * 8);
        }
        asm volatile("cp.async.commit_group;" ::: "memory");
    };

    issue_load(0);

    for (int c = 0; c < 18; c++) {
        if (c + 1 < 18) {
            issue_load(c + 1);
            asm volatile("cp.async.wait_group 1;" ::: "memory");
        } else {
            asm volatile("cp.async.wait_group 0;" ::: "memory");
        }
        __syncthreads();
        int buf = c & 1;
        #pragma unroll
        for (int ks = 0; ks < 4; ks++) {
            uint32_t afrag[4][4];
            #pragma unroll
            for (int mt = 0; mt < 4; mt++) {
                int r = warpM * 64 + mt * 16 + (lane & 15);
                int chunk = ((ks * 2 + (lane >> 4)) ^ (r & 7));
                ldsm_x4(afrag[mt], sA[buf] + (uint32_t)(r * 128 + chunk * 16));
            }
            uint32_t bfrag[2][4];
            #pragma unroll
            for (int bt = 0; bt < 2; bt++) {
                int r = warpN * 32 + bt * 16 + (lane & 15);
                int chunk = ((ks * 2 + (lane >> 4)) ^ (r & 7));
                ldsm_x4(bfrag[bt], sB[buf] + (uint32_t)(r * 128 + chunk * 16));
            }
            #pragma unroll
            for (int mt = 0; mt < 4; mt++)
                #pragma unroll
                for (int nt = 0; nt < 4; nt++) {
                    int bt = nt >> 1, j = nt & 1;
                    mma_bf16(acc[mt][nt], afrag[mt], bfrag[bt][j], bfrag[bt][j + 2]);
                }
        }
        __syncthreads();
    }

    int grow = m0 + warpM * 64 + (lane >> 2);
    int gcol = n0 + warpN * 32 + (lane & 3) * 2;
    #pragma unroll
    for (int mt = 0; mt < 4; mt++) {
        #pragma unroll
        for (int nt = 0; nt < 4; nt++) {
            int gm = grow + mt * 16;
            int gn = gcol + nt * 8;
            if (mode == 0) {
                __nv_bfloat16* Yh = (mat == 0) ? g_qhi : (mat == 1) ? g_khi : g_vhi;
                __nv_bfloat16* Yl = (mat == 0) ? g_qlo : (mat == 1) ? g_klo : g_vlo;
                int b = gm >> 10, nrow = gm & 1023;
                int h = gn >> 6,  dd = gn & 63;
                size_t base = ((size_t)(b * NH + h) << 16) + dd;
                uint32_t hh, ll;
                split_pair(acc[mt][nt][0], acc[mt][nt][1], hh, ll);
                *(uint32_t*)(Yh + base + ((size_t)nrow << 6)) = hh;
                *(uint32_t*)(Yl + base + ((size_t)nrow << 6)) = ll;
                split_pair(acc[mt][nt][2], acc[mt][nt][3], hh, ll);
                *(uint32_t*)(Yh + base + ((size_t)(nrow + 8) << 6)) = hh;
                *(uint32_t*)(Yl + base + ((size_t)(nrow + 8) << 6)) = ll;
            } else {
                *(float2*)(proj_out + (size_t)gm       * DIM + gn) =
                    make_float2(acc[mt][nt][0], acc[mt][nt][1]);
                *(float2*)(proj_out + (size_t)(gm + 8) * DIM + gn) =
                    make_float2(acc[mt][nt][2], acc[mt][nt][3]);
            }
        }
    }
}

// ---------------------------------------------------------------------------
// Tensor-core flash attention, split-bf16 (3-term) for S and PV.
// CTA: 128 q-rows of one (b,h). 8 warps; warp w owns rows [16w, 16w+16).
// Per k-tile (64 keys): S = (qh+ql)(kh+kl)^T (3 terms), +P, online softmax,
// prob split -> (ph+pl)(vh+vl) (3 terms). cp.async double-buffered K/V/P.
// ---------------------------------------------------------------------------
#define AT_STAGE 67584
#define AT_KHI 0
#define AT_KLO 8192
#define AT_VHI 16384
#define AT_VLO 24576
#define AT_P   32768
#define ATTN_SMEM (2*AT_STAGE)

__global__ void __launch_bounds__(256) attn_tc(const float* __restrict__ logit_lambda)
{
    extern __shared__ char smc[];
    uint32_t sb = smem_u32(smc);
    int tid = threadIdx.x, lane = tid & 31, w = tid >> 5;
    int qb0 = blockIdx.x * 128;
    int bh = blockIdx.y;
    int b_ = bh / NH, head = bh % NH;
    size_t base = (size_t)bh << 16;

    const __nv_bfloat16* qh = g_qhi + base;
    const __nv_bfloat16* ql = g_qlo + base;
    const __nv_bfloat16* kh = g_khi + base;
    const __nv_bfloat16* kl = g_klo + base;
    const __nv_bfloat16* vh = g_vhi + base;
    const __nv_bfloat16* vl = g_vlo + base;

    float lam   = 1.0f / (1.0f + __expf(-logit_lambda[0]));
    float scale = lam * 0.125f;

    // ---- preload Q fragments (stage0 first 16KB as staging) ----
    uint32_t qfh[4][4], qfl[4][4];
    #pragma unroll
    for (int pass = 0; pass < 2; pass++) {
        const __nv_bfloat16* src = pass ? ql : qh;
        #pragma unroll
        for (int it = 0; it < 4; it++) {
            int idx = it * 256 + tid;
            int row = idx >> 3, c = idx & 7;
            uint32_t soff = (uint32_t)(row * 128 + ((c ^ (row & 7)) << 4));
            cp_async16(sb + soff, src + (size_t)(qb0 + row) * 64 + c * 8);
        }
        asm volatile("cp.async.commit_group;\n\tcp.async.wait_group 0;" ::: "memory");
        __syncthreads();
        uint32_t (*dst)[4] = pass ? qfl : qfh;
        #pragma unroll
        for (int kk = 0; kk < 4; kk++) {
            int r = w * 16 + (lane & 15);
            int ch = ((kk * 2 + (lane >> 4)) ^ (r & 7));
            ldsm_x4(dst[kk], sb + (uint32_t)(r * 128 + ch * 16));
        }
        __syncthreads();
    }

    auto issue = [&](int kt) {
        uint32_t s0 = sb + (uint32_t)(kt & 1) * AT_STAGE;
        int k0 = kt * 64;
        #pragma unroll
        for (int it = 0; it < 2; it++) {
            int idx = it * 256 + tid;
            int row = idx >> 3, c = idx & 7;
            uint32_t soff = (uint32_t)(row * 128 + ((c ^ (row & 7)) << 4));
            size_t g = (size_t)(k0 + row) * 64 + c * 8;
            cp_async16(s0 + AT_KHI + soff, kh + g);
            cp_async16(s0 + AT_KLO + soff, kl + g);
            cp_async16(s0 + AT_VHI + soff, vh + g);
            cp_async16(s0 + AT_VLO + soff, vl + g);
        }
        #pragma unroll
        for (int it = 0; it < 8; it++) {
            int idx = it * 256 + tid;
            int row = idx >> 4, c = idx & 15;
            cp_async16(s0 + AT_P + (uint32_t)(row * 272 + c * 16),
                       g_pl + (size_t)(qb0 + row) * SEQ + k0 + c * 4);
        }
        asm volatile("cp.async.commit_group;" ::: "memory");
    };

    float m0 = -1e30f, m1 = -1e30f, l0 = 0.f, l1 = 0.f;
    float oacc[8][4];
    #pragma unroll
    for (int j = 0; j < 8; j++)
        #pragma unroll
        for (int i = 0; i < 4; i++) oacc[j][i] = 0.f;

    int g   = lane >> 2;
    int t2  = (lane & 3) * 2;

    issue(0); issue(1);

    for (int kt = 0; kt < 16; kt++) {
        if (kt < 15) asm volatile("cp.async.wait_group 1;" ::: "memory");
        else         asm volatile("cp.async.wait_group 0;" ::: "memory");
        __syncthreads();
        uint32_t s0 = sb + (uint32_t)(kt & 1) * AT_STAGE;
        const float* Pp = (const float*)(smc + (size_t)(kt & 1) * AT_STAGE + AT_P);

        // ---- S = 3-term QK^T ----
        float acc[8][4];
        #pragma unroll
        for (int j = 0; j < 8; j++)
            #pragma unroll
            for (int i = 0; i < 4; i++) acc[j][i] = 0.f;

        #pragma unroll
        for (int kk = 0; kk < 4; kk++) {
            uint32_t bf[4][4];
            #pragma unroll
            for (int bt = 0; bt < 4; bt++) {
                int r = bt * 16 + (lane & 15);
                int ch = ((kk * 2 + (lane >> 4)) ^ (r & 7));
                ldsm_x4(bf[bt], s0 + AT_KHI + (uint32_t)(r * 128 + ch * 16));
            }
            #pragma unroll
            for (int bt = 0; bt < 4; bt++)
                #pragma unroll
                for (int jj = 0; jj < 2; jj++) {
                    mma_bf16(acc[bt*2+jj], qfh[kk], bf[bt][jj], bf[bt][jj+2]);
                    mma_bf16(acc[bt*2+jj], qfl[kk], bf[bt][jj], bf[bt][jj+2]);
                }
            #pragma unroll
            for (int bt = 0; bt < 4; bt++) {
                int r = bt * 16 + (lane & 15);
                int ch = ((kk * 2 + (lane >> 4)) ^ (r & 7));
                ldsm_x4(bf[bt], s0 + AT_KLO + (uint32_t)(r * 128 + ch * 16));
            }
            #pragma unroll
            for (int bt = 0; bt < 4; bt++)
                #pragma unroll
                for (int jj = 0; jj < 2; jj++)
                    mma_bf16(acc[bt*2+jj], qfh[kk], bf[bt][jj], bf[bt][jj+2]);
        }

        // ---- + P, online softmax ----
        int prow0 = (w * 16 + g) * 68;
        int prow1 = prow0 + 8 * 68;
        float rmax0 = -1e30f, rmax1 = -1e30f;
        #pragma unroll
        for (int j = 0; j < 8; j++) {
            int col = t2 + 8 * j;
            acc[j][0] = acc[j][0] * scale + Pp[prow0 + col];
            acc[j][1] = acc[j][1] * scale + Pp[prow0 + col + 1];
            acc[j][2] = acc[j][2] * scale + Pp[prow1 + col];
            acc[j][3] = acc[j][3] * scale + Pp[prow1 + col + 1];
            rmax0 = fmaxf(rmax0, fmaxf(acc[j][0], acc[j][1]));
            rmax1 = fmaxf(rmax1, fmaxf(acc[j][2], acc[j][3]));
        }
        rmax0 = fmaxf(rmax0, __shfl_xor_sync(0xffffffffu, rmax0, 1));
        rmax0 = fmaxf(rmax0, __shfl_xor_sync(0xffffffffu, rmax0, 2));
        rmax1 = fmaxf(rmax1, __shfl_xor_sync(0xffffffffu, rmax1, 1));
        rmax1 = fmaxf(rmax1, __shfl_xor_sync(0xffffffffu, rmax1, 2));
        float nm0 = fmaxf(m0, rmax0), nm1 = fmaxf(m1, rmax1);
        float r0 = __expf(m0 - nm0),  r1 = __expf(m1 - nm1);
        float sum0 = 0.f, sum1 = 0.f;
        #pragma unroll
        for (int j = 0; j < 8; j++) {
            acc[j][0] = __expf(acc[j][0] - nm0);
            acc[j][1] = __expf(acc[j][1] - nm0);
            acc[j][2] = __expf(acc[j][2] - nm1);
            acc[j][3] = __expf(acc[j][3] - nm1);
            sum0 += acc[j][0] + acc[j][1];
            sum1 += acc[j][2] + acc[j][3];
        }
        sum0 += __shfl_xor_sync(0xffffffffu, sum0, 1);
        sum0 += __shfl_xor_sync(0xffffffffu, sum0, 2);
        sum1 += __shfl_xor_sync(0xffffffffu, sum1, 1);
        sum1 += __shfl_xor_sync(0xffffffffu, sum1, 2);
        l0 = l0 * r0 + sum0;  l1 = l1 * r1 + sum1;
        m0 = nm0;             m1 = nm1;
        #pragma unroll
        for (int j = 0; j < 8; j++) {
            oacc[j][0] *= r0; oacc[j][1] *= r0;
            oacc[j][2] *= r1; oacc[j][3] *= r1;
        }

        // ---- O += (ph+pl) (vh+vl) : 3 terms ----
        #pragma unroll
        for (int kk = 0; kk < 4; kk++) {
            uint32_t ah[4], al[4];
            split_pair(acc[2*kk][0],   acc[2*kk][1],   ah[0], al[0]);
            split_pair(acc[2*kk][2],   acc[2*kk][3],   ah[1], al[1]);
            split_pair(acc[2*kk+1][0], acc[2*kk+1][1], ah[2], al[2]);
            split_pair(acc[2*kk+1][2], acc[2*kk+1][3], ah[3], al[3]);

            uint32_t bv[4][4];
            #pragma unroll
            for (int ntp = 0; ntp < 4; ntp++) {
                int r = kk * 16 + (lane & 15);
                int ch = ((ntp * 2 + (lane >> 4)) ^ (r & 7));
                ldsm_x4_t(bv[ntp], s0 + AT_VHI + (uint32_t)(r * 128 + ch * 16));
            }
            #pragma unroll
            for (int ntp = 0; ntp < 4; ntp++) {
                mma_bf16(oacc[2*ntp],   ah, bv[ntp][0], bv[ntp][1]);
                mma_bf16(oacc[2*ntp+1], ah, bv[ntp][2], bv[ntp][3]);
                mma_bf16(oacc[2*ntp],   al, bv[ntp][0], bv[ntp][1]);
                mma_bf16(oacc[2*ntp+1], al, bv[ntp][2], bv[ntp][3]);
            }
            #pragma unroll
            for (int ntp = 0; ntp < 4; ntp++) {
                int r = kk * 16 + (lane & 15);
                int ch = ((ntp * 2 + (lane >> 4)) ^ (r & 7));
                ldsm_x4_t(bv[ntp], s0 + AT_VLO + (uint32_t)(r * 128 + ch * 16));
            }
            #pragma unroll
            for (int ntp = 0; ntp < 4; ntp++) {
                mma_bf16(oacc[2*ntp],   ah, bv[ntp][0], bv[ntp][1]);
                mma_bf16(oacc[2*ntp+1], ah, bv[ntp][2], bv[ntp][3]);
            }
        }

        __syncthreads();
        if (kt + 2 < 16) issue(kt + 2);
    }

    // ---- epilogue: O/l -> bf16 hi/lo into g_aohi/g_aolo ----
    float i0 = 1.0f / l0, i1 = 1.0f / l1;
    int row0 = b_ * SEQ + qb0 + w * 16 + g;
    size_t ob0 = (size_t)row0 * DIM + head * 64;
    size_t ob1 = ob0 + (size_t)8 * DIM;
    #pragma unroll
    for (int j = 0; j < 8; j++) {
        int col = t2 + 8 * j;
        uint32_t hh, ll;
        split_pair(oacc[j][0] * i0, oacc[j][1] * i0, hh, ll);
        *(uint32_t*)(g_aohi + ob0 + col) = hh;
        *(uint32_t*)(g_aolo + ob0 + col) = ll;
        split_pair(oacc[j][2] * i1, oacc[j][3] * i1, hh, ll);
        *(uint32_t*)(g_aohi + ob1 + col) = hh;
        *(uint32_t*)(g_aolo + ob1 + col) = ll;
    }
}

// ---------------------------------------------------------------------------
extern "C" void kernel_launch(void* const* d_in, const int* in_sizes, int n_in,
                              void* d_out, int out_size)
{
    const float* x  = (const float*)d_in[0];
    const float* Wq = (const float*)d_in[1];
    const float* Wk = (const float*)d_in[2];
    const float* Wv = (const float*)d_in[3];
    const float* Wp = (const float*)d_in[4];
    const float* ll = (const float*)d_in[5];
    const float* ls = (const float*)d_in[6];
    float* out = (float*)d_out;

    cudaFuncSetAttribute(tc_gemm,
                         cudaFuncAttributeMaxDynamicSharedMemorySize, GEMM_SMEM);
    cudaFuncSetAttribute(attn_tc,
                         cudaFuncAttributeMaxDynamicSharedMemorySize, ATTN_SMEM);

    __nv_bfloat16 *xhi, *xlo, *aohi, *aolo, *whi, *wlo;
    cudaGetSymbolAddress((void**)&xhi,  g_xhi);
    cudaGetSymbolAddress((void**)&xlo,  g_xlo);
    cudaGetSymbolAddress((void**)&aohi, g_aohi);
    cudaGetSymbolAddress((void**)&aolo, g_aolo);
    cudaGetSymbolAddress((void**)&whi,  g_whi);
    cudaGetSymbolAddress((void**)&wlo,  g_wlo);

    pos_kernel<<<SEQ, 256>>>(ll, ls);

    convert_split<<<(MTOT*DIM + 255)/256, 256>>>(x, xhi, xlo, MTOT*DIM);
    convert_split<<<(DIM*DIM + 255)/256, 256>>>(Wq, whi + 0*DIM*DIM, wlo + 0*DIM*DIM, DIM*DIM);
    convert_split<<<(DIM*DIM + 255)/256, 256>>>(Wk, whi + 1*DIM*DIM, wlo + 1*DIM*DIM, DIM*DIM);
    convert_split<<<(DIM*DIM + 255)/256, 256>>>(Wv, whi + 2*DIM*DIM, wlo + 2*DIM*DIM, DIM*DIM);
    convert_split<<<(DIM*DIM + 255)/256, 256>>>(Wp, whi + 3*DIM*DIM, wlo + 3*DIM*DIM, DIM*DIM);

    tc_gemm<<<dim3(64, 3, 3), 256, GEMM_SMEM>>>(xhi, xlo, whi, wlo, nullptr, 0);

    attn_tc<<<dim3(SEQ/128, BATCH*NH), 256, ATTN_SMEM>>>(ll);

    tc_gemm<<<dim3(64, 3, 1), 256, GEMM_SMEM>>>(aohi, aolo,
                                                whi + 3*DIM*DIM, wlo + 3*DIM*DIM,
                                                out, 1);
}

// round 7
// speedup vs baseline: 2.2760x; 1.0007x over previous
#include <cuda_runtime.h>
#include <cuda_bf16.h>
#include <math.h>
#include <stdint.h>

#define DIM 384
#define NH 6
#define DH 64
#define BATCH 8
#define SEQ 1024
#define MTOT (BATCH*SEQ)

// ---------------- scratch (device globals; no allocation allowed) ----------
__device__ float g_pl[SEQ*SEQ];

__device__ __nv_bfloat16 g_qhi[BATCH*NH*SEQ*DH];
__device__ __nv_bfloat16 g_qlo[BATCH*NH*SEQ*DH];
__device__ __nv_bfloat16 g_khi[BATCH*NH*SEQ*DH];
__device__ __nv_bfloat16 g_klo[BATCH*NH*SEQ*DH];
__device__ __nv_bfloat16 g_vhi[BATCH*NH*SEQ*DH];
__device__ __nv_bfloat16 g_vlo[BATCH*NH*SEQ*DH];

__device__ __nv_bfloat16 g_xhi [MTOT*DIM];
__device__ __nv_bfloat16 g_xlo [MTOT*DIM];
__device__ __nv_bfloat16 g_aohi[MTOT*DIM];
__device__ __nv_bfloat16 g_aolo[MTOT*DIM];
__device__ __nv_bfloat16 g_whi [4*DIM*DIM];
__device__ __nv_bfloat16 g_wlo [4*DIM*DIM];

// ---------------- helpers ---------------------------------------------------
static __device__ __forceinline__ uint32_t smem_u32(const void* p) {
    return (uint32_t)__cvta_generic_to_shared(p);
}
static __device__ __forceinline__ void ldsm_x4(uint32_t* r, uint32_t addr) {
    asm volatile("ldmatrix.sync.aligned.m8n8.x4.shared.b16 {%0,%1,%2,%3}, [%4];"
                 : "=r"(r[0]), "=r"(r[1]), "=r"(r[2]), "=r"(r[3]) : "r"(addr));
}
static __device__ __forceinline__ void ldsm_x4_t(uint32_t* r, uint32_t addr) {
    asm volatile("ldmatrix.sync.aligned.m8n8.x4.trans.shared.b16 {%0,%1,%2,%3}, [%4];"
                 : "=r"(r[0]), "=r"(r[1]), "=r"(r[2]), "=r"(r[3]) : "r"(addr));
}
static __device__ __forceinline__ void mma_bf16(float* d, const uint32_t* a,
                                                uint32_t b0, uint32_t b1) {
    asm volatile(
        "mma.sync.aligned.m16n8k16.row.col.f32.bf16.bf16.f32 "
        "{%0,%1,%2,%3}, {%4,%5,%6,%7}, {%8,%9}, {%0,%1,%2,%3};"
        : "+f"(d[0]), "+f"(d[1]), "+f"(d[2]), "+f"(d[3])
        : "r"(a[0]), "r"(a[1]), "r"(a[2]), "r"(a[3]), "r"(b0), "r"(b1));
}
static __device__ __forceinline__ void cp_async16(uint32_t dst, const void* src) {
    asm volatile("cp.async.cg.shared.global [%0], [%1], 16;" :: "r"(dst), "l"(src));
}
// pack (lo=a, hi=b) into bf16x2; little-endian: low half = element at col 2t.
static __device__ __forceinline__ uint32_t pack_bf16(float a, float b) {
    uint32_t r;
    asm("cvt.rn.bf16x2.f32 %0, %1, %2;" : "=r"(r) : "f"(b), "f"(a));
    return r;
}
static __device__ __forceinline__ void split_pair(float a, float b,
                                                  uint32_t& hi, uint32_t& lo) {
    hi = pack_bf16(a, b);
    float fa = __uint_as_float(hi << 16);
    float fb = __uint_as_float(hi & 0xffff0000u);
    lo = pack_bf16(a - fa, b - fb);
}

// ---------------------------------------------------------------------------
// Positional kernel: g_pl[i][j] = (1-lam) * exp(-dist2(i,j) / (2 sigma^2))
// ---------------------------------------------------------------------------
__global__ void pos_kernel(const float* __restrict__ logit_lambda,
                           const float* __restrict__ log_sigma)
{
    float ls  = log_sigma[0];
    float sig = log1pf(expf(ls)) + 1e-6f;
    float inv = 1.0f / (2.0f * sig * sig);
    float lam = 1.0f / (1.0f + expf(-logit_lambda[0]));
    float oml = 1.0f - lam;

    int i = blockIdx.x;
    float yi = (float)(i >> 5), xi = (float)(i & 31);
    for (int j = threadIdx.x; j < SEQ; j += blockDim.x) {
        float yj = (float)(j >> 5), xj = (float)(j & 31);
        float dy = yi - yj, dx = xi - xj;
        g_pl[i*SEQ + j] = oml * __expf(-(dy*dy + dx*dx) * inv);
    }
}

// ---------------------------------------------------------------------------
// fp32 -> (bf16 hi, bf16 lo) split
// ---------------------------------------------------------------------------
__global__ void convert_split(const float* __restrict__ src,
                              __nv_bfloat16* __restrict__ hi,
                              __nv_bfloat16* __restrict__ lo, int n)
{
    int i = blockIdx.x * 256 + threadIdx.x;
    if (i < n) {
        float v = src[i];
        __nv_bfloat16 h = __float2bfloat16(v);
        hi[i] = h;
        lo[i] = __float2bfloat16(v - __bfloat162float(h));
    }
}

// ---------------------------------------------------------------------------
// mma.sync bf16-split GEMM: D[M,N] = A @ B^T,  A = Ahi+Alo, B = Bhi+Blo
// mode 0: split D -> (g_q/g_k/g_v)(hi,lo) in (b,h,n,dh) bf16 layout
// mode 1: write fp32 [M, DIM] into proj_out
// ---------------------------------------------------------------------------
#define GEMM_SMEM 65536

__global__ void __launch_bounds__(256) tc_gemm(
    const __nv_bfloat16* __restrict__ Ahi,
    const __nv_bfloat16* __restrict__ Alo,
    const __nv_bfloat16* __restrict__ Bhi_all,
    const __nv_bfloat16* __restrict__ Blo_all,
    float* __restrict__ proj_out,
    int mode)
{
    extern __shared__ char smc[];
    uint32_t sb = smem_u32(smc);
    const uint32_t sA[2] = {sb,           sb + 16384u};
    const uint32_t sB[2] = {sb + 32768u,  sb + 49152u};

    int tid = threadIdx.x, lane = tid & 31, wid = tid >> 5;
    int warpM = wid >> 2, warpN = wid & 3;            // 2 x 4
    int m0 = blockIdx.x * 128, n0 = blockIdx.y * 128, mat = blockIdx.z;

    const __nv_bfloat16* Bhi = Bhi_all + (size_t)mat * DIM * DIM;
    const __nv_bfloat16* Blo = Blo_all + (size_t)mat * DIM * DIM;

    float acc[4][4][4];
    #pragma unroll
    for (int i = 0; i < 4; i++)
        #pragma unroll
        for (int j = 0; j < 4; j++)
            #pragma unroll
            for (int k = 0; k < 4; k++) acc[i][j][k] = 0.f;

    auto issue_load = [&](int c) {
        int buf = c & 1;
        int seg = c / 6, kc = c - seg * 6, koff = kc * 64;
        const __nv_bfloat16* Ag = (seg == 2) ? Alo : Ahi;
        const __nv_bfloat16* Bg = (seg == 1) ? Blo : Bhi;
        #pragma unroll
        for (int it = 0; it < 4; it++) {
            int idx = it * 256 + tid;
            int row = idx >> 3, cc = idx & 7;
            uint32_t soff = (uint32_t)(row * 128 + ((cc ^ (row & 7)) << 4));
            cp_async16(sA[buf] + soff, Ag + (size_t)(m0 + row) * DIM + koff + cc * 8);
            cp_async16(sB[buf] + soff, Bg + (size_t)(n0 + row) * DIM + koff + cc * 8);
        }
        asm volatile("cp.async.commit_group;" ::: "memory");
    };

    issue_load(0);

    for (int c = 0; c < 18; c++) {
        if (c + 1 < 18) {
            issue_load(c + 1);
            asm volatile("cp.async.wait_group 1;" ::: "memory");
        } else {
            asm volatile("cp.async.wait_group 0;" ::: "memory");
        }
        __syncthreads();
        int buf = c & 1;
        #pragma unroll
        for (int ks = 0; ks < 4; ks++) {
            uint32_t afrag[4][4];
            #pragma unroll
            for (int mt = 0; mt < 4; mt++) {
                int r = warpM * 64 + mt * 16 + (lane & 15);
                int chunk = ((ks * 2 + (lane >> 4)) ^ (r & 7));
                ldsm_x4(afrag[mt], sA[buf] + (uint32_t)(r * 128 + chunk * 16));
            }
            uint32_t bfrag[2][4];
            #pragma unroll
            for (int bt = 0; bt < 2; bt++) {
                int r = warpN * 32 + bt * 16 + (lane & 15);
                int chunk = ((ks * 2 + (lane >> 4)) ^ (r & 7));
                ldsm_x4(bfrag[bt], sB[buf] + (uint32_t)(r * 128 + chunk * 16));
            }
            #pragma unroll
            for (int mt = 0; mt < 4; mt++)
                #pragma unroll
                for (int nt = 0; nt < 4; nt++) {
                    int bt = nt >> 1, j = nt & 1;
                    mma_bf16(acc[mt][nt], afrag[mt], bfrag[bt][j], bfrag[bt][j + 2]);
                }
        }
        __syncthreads();
    }

    int grow = m0 + warpM * 64 + (lane >> 2);
    int gcol = n0 + warpN * 32 + (lane & 3) * 2;
    #pragma unroll
    for (int mt = 0; mt < 4; mt++) {
        #pragma unroll
        for (int nt = 0; nt < 4; nt++) {
            int gm = grow + mt * 16;
            int gn = gcol + nt * 8;
            if (mode == 0) {
                __nv_bfloat16* Yh = (mat == 0) ? g_qhi : (mat == 1) ? g_khi : g_vhi;
                __nv_bfloat16* Yl = (mat == 0) ? g_qlo : (mat == 1) ? g_klo : g_vlo;
                int b = gm >> 10, nrow = gm & 1023;
                int h = gn >> 6,  dd = gn & 63;
                size_t base = ((size_t)(b * NH + h) << 16) + dd;
                uint32_t hh, ll;
                split_pair(acc[mt][nt][0], acc[mt][nt][1], hh, ll);
                *(uint32_t*)(Yh + base + ((size_t)nrow << 6)) = hh;
                *(uint32_t*)(Yl + base + ((size_t)nrow << 6)) = ll;
                split_pair(acc[mt][nt][2], acc[mt][nt][3], hh, ll);
                *(uint32_t*)(Yh + base + ((size_t)(nrow + 8) << 6)) = hh;
                *(uint32_t*)(Yl + base + ((size_t)(nrow + 8) << 6)) = ll;
            } else {
                *(float2*)(proj_out + (size_t)gm       * DIM + gn) =
                    make_float2(acc[mt][nt][0], acc[mt][nt][1]);
                *(float2*)(proj_out + (size_t)(gm + 8) * DIM + gn) =
                    make_float2(acc[mt][nt][2], acc[mt][nt][3]);
            }
        }
    }
}

// ---------------------------------------------------------------------------
// Tensor-core flash attention, split-bf16 (3-term) for S and PV.
// CTA: 128 q-rows of one (b,h). 8 warps; warp w owns rows [16w, 16w+16).
// Per k-tile (64 keys): S = (qh+ql)(kh+kl)^T (3 terms), +P, online softmax,
// prob split -> (ph+pl)(vh+vl) (3 terms). cp.async double-buffered K/V/P.
// ---------------------------------------------------------------------------
#define AT_STAGE 67584
#define AT_KHI 0
#define AT_KLO 8192
#define AT_VHI 16384
#define AT_VLO 24576
#define AT_P   32768
#define ATTN_SMEM (2*AT_STAGE)

__global__ void __launch_bounds__(256) attn_tc(const float* __restrict__ logit_lambda)
{
    extern __shared__ char smc[];
    uint32_t sb = smem_u32(smc);
    int tid = threadIdx.x, lane = tid & 31, w = tid >> 5;
    int qb0 = blockIdx.x * 128;
    int bh = blockIdx.y;
    int b_ = bh / NH, head = bh % NH;
    size_t base = (size_t)bh << 16;

    const __nv_bfloat16* qh = g_qhi + base;
    const __nv_bfloat16* ql = g_qlo + base;
    const __nv_bfloat16* kh = g_khi + base;
    const __nv_bfloat16* kl = g_klo + base;
    const __nv_bfloat16* vh = g_vhi + base;
    const __nv_bfloat16* vl = g_vlo + base;

    float lam   = 1.0f / (1.0f + __expf(-logit_lambda[0]));
    float scale = lam * 0.125f;

    // ---- preload Q fragments (stage0 first 16KB as staging) ----
    uint32_t qfh[4][4], qfl[4][4];
    #pragma unroll
    for (int pass = 0; pass < 2; pass++) {
        const __nv_bfloat16* src = pass ? ql : qh;
        #pragma unroll
        for (int it = 0; it < 4; it++) {
            int idx = it * 256 + tid;
            int row = idx >> 3, c = idx & 7;
            uint32_t soff = (uint32_t)(row * 128 + ((c ^ (row & 7)) << 4));
            cp_async16(sb + soff, src + (size_t)(qb0 + row) * 64 + c * 8);
        }
        asm volatile("cp.async.commit_group;\n\tcp.async.wait_group 0;" ::: "memory");
        __syncthreads();
        uint32_t (*dst)[4] = pass ? qfl : qfh;
        #pragma unroll
        for (int kk = 0; kk < 4; kk++) {
            int r = w * 16 + (lane & 15);
            int ch = ((kk * 2 + (lane >> 4)) ^ (r & 7));
            ldsm_x4(dst[kk], sb + (uint32_t)(r * 128 + ch * 16));
        }
        __syncthreads();
    }

    auto issue = [&](int kt) {
        uint32_t s0 = sb + (uint32_t)(kt & 1) * AT_STAGE;
        int k0 = kt * 64;
        #pragma unroll
        for (int it = 0; it < 2; it++) {
            int idx = it * 256 + tid;
            int row = idx >> 3, c = idx & 7;
            uint32_t soff = (uint32_t)(row * 128 + ((c ^ (row & 7)) << 4));
            size_t g = (size_t)(k0 + row) * 64 + c * 8;
            cp_async16(s0 + AT_KHI + soff, kh + g);
            cp_async16(s0 + AT_KLO + soff, kl + g);
            cp_async16(s0 + AT_VHI + soff, vh + g);
            cp_async16(s0 + AT_VLO + soff, vl + g);
        }
        #pragma unroll
        for (int it = 0; it < 8; it++) {
            int idx = it * 256 + tid;
            int row = idx >> 4, c = idx & 15;
            cp_async16(s0 + AT_P + (uint32_t)(row * 272 + c * 16),
                       g_pl + (size_t)(qb0 + row) * SEQ + k0 + c * 4);
        }
        asm volatile("cp.async.commit_group;" ::: "memory");
    };

    float m0 = -1e30f, m1 = -1e30f, l0 = 0.f, l1 = 0.f;
    float oacc[8][4];
    #pragma unroll
    for (int j = 0; j < 8; j++)
        #pragma unroll
        for (int i = 0; i < 4; i++) oacc[j][i] = 0.f;

    int g   = lane >> 2;
    int t2  = (lane & 3) * 2;

    issue(0); issue(1);

    for (int kt = 0; kt < 16; kt++) {
        if (kt < 15) asm volatile("cp.async.wait_group 1;" ::: "memory");
        else         asm volatile("cp.async.wait_group 0;" ::: "memory");
        __syncthreads();
        uint32_t s0 = sb + (uint32_t)(kt & 1) * AT_STAGE;
        const float* Pp = (const float*)(smc + (size_t)(kt & 1) * AT_STAGE + AT_P);

        // ---- S = 3-term QK^T ----
        float acc[8][4];
        #pragma unroll
        for (int j = 0; j < 8; j++)
            #pragma unroll
            for (int i = 0; i < 4; i++) acc[j][i] = 0.f;

        #pragma unroll
        for (int kk = 0; kk < 4; kk++) {
            uint32_t bf[4][4];
            #pragma unroll
            for (int bt = 0; bt < 4; bt++) {
                int r = bt * 16 + (lane & 15);
                int ch = ((kk * 2 + (lane >> 4)) ^ (r & 7));
                ldsm_x4(bf[bt], s0 + AT_KHI + (uint32_t)(r * 128 + ch * 16));
            }
            #pragma unroll
            for (int bt = 0; bt < 4; bt++)
                #pragma unroll
                for (int jj = 0; jj < 2; jj++) {
                    mma_bf16(acc[bt*2+jj], qfh[kk], bf[bt][jj], bf[bt][jj+2]);
                    mma_bf16(acc[bt*2+jj], qfl[kk], bf[bt][jj], bf[bt][jj+2]);
                }
            #pragma unroll
            for (int bt = 0; bt < 4; bt++) {
                int r = bt * 16 + (lane & 15);
                int ch = ((kk * 2 + (lane >> 4)) ^ (r & 7));
                ldsm_x4(bf[bt], s0 + AT_KLO + (uint32_t)(r * 128 + ch * 16));
            }
            #pragma unroll
            for (int bt = 0; bt < 4; bt++)
                #pragma unroll
                for (int jj = 0; jj < 2; jj++)
                    mma_bf16(acc[bt*2+jj], qfh[kk], bf[bt][jj], bf[bt][jj+2]);
        }

        // ---- + P, online softmax ----
        int prow0 = (w * 16 + g) * 68;
        int prow1 = prow0 + 8 * 68;
        float rmax0 = -1e30f, rmax1 = -1e30f;
        #pragma unroll
        for (int j = 0; j < 8; j++) {
            int col = t2 + 8 * j;
            acc[j][0] = acc[j][0] * scale + Pp[prow0 + col];
            acc[j][1] = acc[j][1] * scale + Pp[prow0 + col + 1];
            acc[j][2] = acc[j][2] * scale + Pp[prow1 + col];
            acc[j][3] = acc[j][3] * scale + Pp[prow1 + col + 1];
            rmax0 = fmaxf(rmax0, fmaxf(acc[j][0], acc[j][1]));
            rmax1 = fmaxf(rmax1, fmaxf(acc[j][2], acc[j][3]));
        }
        rmax0 = fmaxf(rmax0, __shfl_xor_sync(0xffffffffu, rmax0, 1));
        rmax0 = fmaxf(rmax0, __shfl_xor_sync(0xffffffffu, rmax0, 2));
        rmax1 = fmaxf(rmax1, __shfl_xor_sync(0xffffffffu, rmax1, 1));
        rmax1 = fmaxf(rmax1, __shfl_xor_sync(0xffffffffu, rmax1, 2));
        float nm0 = fmaxf(m0, rmax0), nm1 = fmaxf(m1, rmax1);
        float r0 = __expf(m0 - nm0),  r1 = __expf(m1 - nm1);
        float sum0 = 0.f, sum1 = 0.f;
        #pragma unroll
        for (int j = 0; j < 8; j++) {
            acc[j][0] = __expf(acc[j][0] - nm0);
            acc[j][1] = __expf(acc[j][1] - nm0);
            acc[j][2] = __expf(acc[j][2] - nm1);
            acc[j][3] = __expf(acc[j][3] - nm1);
            sum0 += acc[j][0] + acc[j][1];
            sum1 += acc[j][2] + acc[j][3];
        }
        sum0 += __shfl_xor_sync(0xffffffffu, sum0, 1);
        sum0 += __shfl_xor_sync(0xffffffffu, sum0, 2);
        sum1 += __shfl_xor_sync(0xffffffffu, sum1, 1);
        sum1 += __shfl_xor_sync(0xffffffffu, sum1, 2);
        l0 = l0 * r0 + sum0;  l1 = l1 * r1 + sum1;
        m0 = nm0;             m1 = nm1;
        #pragma unroll
        for (int j = 0; j < 8; j++) {
            oacc[j][0] *= r0; oacc[j][1] *= r0;
            oacc[j][2] *= r1; oacc[j][3] *= r1;
        }

        // ---- O += (ph+pl) (vh+vl) : 3 terms ----
        #pragma unroll
        for (int kk = 0; kk < 4; kk++) {
            uint32_t ah[4], al[4];
            split_pair(acc[2*kk][0],   acc[2*kk][1],   ah[0], al[0]);
            split_pair(acc[2*kk][2],   acc[2*kk][3],   ah[1], al[1]);
            split_pair(acc[2*kk+1][0], acc[2*kk+1][1], ah[2], al[2]);
            split_pair(acc[2*kk+1][2], acc[2*kk+1][3], ah[3], al[3]);

            uint32_t bv[4][4];
            #pragma unroll
            for (int ntp = 0; ntp < 4; ntp++) {
                int r = kk * 16 + (lane & 15);
                int ch = ((ntp * 2 + (lane >> 4)) ^ (r & 7));
                ldsm_x4_t(bv[ntp], s0 + AT_VHI + (uint32_t)(r * 128 + ch * 16));
            }
            #pragma unroll
            for (int ntp = 0; ntp < 4; ntp++) {
                mma_bf16(oacc[2*ntp],   ah, bv[ntp][0], bv[ntp][1]);
                mma_bf16(oacc[2*ntp+1], ah, bv[ntp][2], bv[ntp][3]);
                mma_bf16(oacc[2*ntp],   al, bv[ntp][0], bv[ntp][1]);
                mma_bf16(oacc[2*ntp+1], al, bv[ntp][2], bv[ntp][3]);
            }
            #pragma unroll
            for (int ntp = 0; ntp < 4; ntp++) {
                int r = kk * 16 + (lane & 15);
                int ch = ((ntp * 2 + (lane >> 4)) ^ (r & 7));
                ldsm_x4_t(bv[ntp], s0 + AT_VLO + (uint32_t)(r * 128 + ch * 16));
            }
            #pragma unroll
            for (int ntp = 0; ntp < 4; ntp++) {
                mma_bf16(oacc[2*ntp],   ah, bv[ntp][0], bv[ntp][1]);
                mma_bf16(oacc[2*ntp+1], ah, bv[ntp][2], bv[ntp][3]);
            }
        }

        __syncthreads();
        if (kt + 2 < 16) issue(kt + 2);
    }

    // ---- epilogue: O/l -> bf16 hi/lo into g_aohi/g_aolo ----
    float i0 = 1.0f / l0, i1 = 1.0f / l1;
    int row0 = b_ * SEQ + qb0 + w * 16 + g;
    size_t ob0 = (size_t)row0 * DIM + head * 64;
    size_t ob1 = ob0 + (size_t)8 * DIM;
    #pragma unroll
    for (int j = 0; j < 8; j++) {
        int col = t2 + 8 * j;
        uint32_t hh, ll;
        split_pair(oacc[j][0] * i0, oacc[j][1] * i0, hh, ll);
        *(uint32_t*)(g_aohi + ob0 + col) = hh;
        *(uint32_t*)(g_aolo + ob0 + col) = ll;
        split_pair(oacc[j][2] * i1, oacc[j][3] * i1, hh, ll);
        *(uint32_t*)(g_aohi + ob1 + col) = hh;
        *(uint32_t*)(g_aolo + ob1 + col) = ll;
    }
}

// ---------------------------------------------------------------------------
extern "C" void kernel_launch(void* const* d_in, const int* in_sizes, int n_in,
                              void* d_out, int out_size)
{
    const float* x  = (const float*)d_in[0];
    const float* Wq = (const float*)d_in[1];
    const float* Wk = (const float*)d_in[2];
    const float* Wv = (const float*)d_in[3];
    const float* Wp = (const float*)d_in[4];
    const float* ll = (const float*)d_in[5];
    const float* ls = (const float*)d_in[6];
    float* out = (float*)d_out;

    cudaFuncSetAttribute(tc_gemm,
                         cudaFuncAttributeMaxDynamicSharedMemorySize, GEMM_SMEM);
    cudaFuncSetAttribute(attn_tc,
                         cudaFuncAttributeMaxDynamicSharedMemorySize, ATTN_SMEM);

    __nv_bfloat16 *xhi, *xlo, *aohi, *aolo, *whi, *wlo;
    cudaGetSymbolAddress((void**)&xhi,  g_xhi);
    cudaGetSymbolAddress((void**)&xlo,  g_xlo);
    cudaGetSymbolAddress((void**)&aohi, g_aohi);
    cudaGetSymbolAddress((void**)&aolo, g_aolo);
    cudaGetSymbolAddress((void**)&whi,  g_whi);
    cudaGetSymbolAddress((void**)&wlo,  g_wlo);

    pos_kernel<<<SEQ, 256>>>(ll, ls);

    convert_split<<<(MTOT*DIM + 255)/256, 256>>>(x, xhi, xlo, MTOT*DIM);
    convert_split<<<(DIM*DIM + 255)/256, 256>>>(Wq, whi + 0*DIM*DIM, wlo + 0*DIM*DIM, DIM*DIM);
    convert_split<<<(DIM*DIM + 255)/256, 256>>>(Wk, whi + 1*DIM*DIM, wlo + 1*DIM*DIM, DIM*DIM);
    convert_split<<<(DIM*DIM + 255)/256, 256>>>(Wv, whi + 2*DIM*DIM, wlo + 2*DIM*DIM, DIM*DIM);
    convert_split<<<(DIM*DIM + 255)/256, 256>>>(Wp, whi + 3*DIM*DIM, wlo + 3*DIM*DIM, DIM*DIM);

    tc_gemm<<<dim3(64, 3, 3), 256, GEMM_SMEM>>>(xhi, xlo, whi, wlo, nullptr, 0);

    attn_tc<<<dim3(SEQ/128, BATCH*NH), 256, ATTN_SMEM>>>(ll);

    tc_gemm<<<dim3(64, 3, 1), 256, GEMM_SMEM>>>(aohi, aolo,
                                                whi + 3*DIM*DIM, wlo + 3*DIM*DIM,
                                                out, 1);
}

// round 8
// speedup vs baseline: 2.2831x; 1.0031x over previous
#include <cuda_runtime.h>
#include <cuda_bf16.h>
#include <math.h>
#include <stdint.h>

#define DIM 384
#define NH 6
#define DH 64
#define BATCH 8
#define SEQ 1024
#define MTOT (BATCH*SEQ)

// ---------------- scratch (device globals; no allocation allowed) ----------
__device__ float g_pl[SEQ*SEQ];

__device__ __nv_bfloat16 g_qhi[BATCH*NH*SEQ*DH];
__device__ __nv_bfloat16 g_qlo[BATCH*NH*SEQ*DH];
__device__ __nv_bfloat16 g_khi[BATCH*NH*SEQ*DH];
__device__ __nv_bfloat16 g_klo[BATCH*NH*SEQ*DH];
__device__ __nv_bfloat16 g_vhi[BATCH*NH*SEQ*DH];
__device__ __nv_bfloat16 g_vlo[BATCH*NH*SEQ*DH];

__device__ __nv_bfloat16 g_xhi [MTOT*DIM];
__device__ __nv_bfloat16 g_xlo [MTOT*DIM];
__device__ __nv_bfloat16 g_aohi[MTOT*DIM];
__device__ __nv_bfloat16 g_aolo[MTOT*DIM];
__device__ __nv_bfloat16 g_whi [4*DIM*DIM];
__device__ __nv_bfloat16 g_wlo [4*DIM*DIM];

// ---------------- helpers ---------------------------------------------------
static __device__ __forceinline__ uint32_t smem_u32(const void* p) {
    return (uint32_t)__cvta_generic_to_shared(p);
}
static __device__ __forceinline__ void ldsm_x4(uint32_t* r, uint32_t addr) {
    asm volatile("ldmatrix.sync.aligned.m8n8.x4.shared.b16 {%0,%1,%2,%3}, [%4];"
                 : "=r"(r[0]), "=r"(r[1]), "=r"(r[2]), "=r"(r[3]) : "r"(addr));
}
static __device__ __forceinline__ void ldsm_x4_t(uint32_t* r, uint32_t addr) {
    asm volatile("ldmatrix.sync.aligned.m8n8.x4.trans.shared.b16 {%0,%1,%2,%3}, [%4];"
                 : "=r"(r[0]), "=r"(r[1]), "=r"(r[2]), "=r"(r[3]) : "r"(addr));
}
static __device__ __forceinline__ void mma_bf16(float* d, const uint32_t* a,
                                                uint32_t b0, uint32_t b1) {
    asm volatile(
        "mma.sync.aligned.m16n8k16.row.col.f32.bf16.bf16.f32 "
        "{%0,%1,%2,%3}, {%4,%5,%6,%7}, {%8,%9}, {%0,%1,%2,%3};"
        : "+f"(d[0]), "+f"(d[1]), "+f"(d[2]), "+f"(d[3])
        : "r"(a[0]), "r"(a[1]), "r"(a[2]), "r"(a[3]), "r"(b0), "r"(b1));
}
static __device__ __forceinline__ void cp_async16(uint32_t dst, const void* src) {
    asm volatile("cp.async.cg.shared.global [%0], [%1], 16;" :: "r"(dst), "l"(src));
}
// pack (lo=a, hi=b) into bf16x2; little-endian: low half = element at col 2t.
static __device__ __forceinline__ uint32_t pack_bf16(float a, float b) {
    uint32_t r;
    asm("cvt.rn.bf16x2.f32 %0, %1, %2;" : "=r"(r) : "f"(b), "f"(a));
    return r;
}
static __device__ __forceinline__ void split_pair(float a, float b,
                                                  uint32_t& hi, uint32_t& lo) {
    hi = pack_bf16(a, b);
    float fa = __uint_as_float(hi << 16);
    float fb = __uint_as_float(hi & 0xffff0000u);
    lo = pack_bf16(a - fa, b - fb);
}

// ---------------------------------------------------------------------------
// Positional kernel: g_pl[i][j] = (1-lam) * exp(-dist2(i,j) / (2 sigma^2))
// ---------------------------------------------------------------------------
__global__ void pos_kernel(const float* __restrict__ logit_lambda,
                           const float* __restrict__ log_sigma)
{
    float ls  = log_sigma[0];
    float sig = log1pf(expf(ls)) + 1e-6f;
    float inv = 1.0f / (2.0f * sig * sig);
    float lam = 1.0f / (1.0f + expf(-logit_lambda[0]));
    float oml = 1.0f - lam;

    int i = blockIdx.x;
    float yi = (float)(i >> 5), xi = (float)(i & 31);
    for (int j = threadIdx.x; j < SEQ; j += blockDim.x) {
        float yj = (float)(j >> 5), xj = (float)(j & 31);
        float dy = yi - yj, dx = xi - xj;
        g_pl[i*SEQ + j] = oml * __expf(-(dy*dy + dx*dx) * inv);
    }
}

// ---------------------------------------------------------------------------
// fp32 -> (bf16 hi, bf16 lo) split
// ---------------------------------------------------------------------------
__global__ void convert_split(const float* __restrict__ src,
                              __nv_bfloat16* __restrict__ hi,
                              __nv_bfloat16* __restrict__ lo, int n)
{
    int i = blockIdx.x * 256 + threadIdx.x;
    if (i < n) {
        float v = src[i];
        __nv_bfloat16 h = __float2bfloat16(v);
        hi[i] = h;
        lo[i] = __float2bfloat16(v - __bfloat162float(h));
    }
}

// ---------------------------------------------------------------------------
// mma.sync bf16-split GEMM: D[M,N] = A @ B^T,  A = Ahi+Alo, B = Bhi+Blo
// mode 0: split D -> (g_q/g_k/g_v)(hi,lo) in (b,h,n,dh) bf16 layout
// mode 1: write fp32 [M, DIM] into proj_out
// ---------------------------------------------------------------------------
#define GEMM_SMEM 65536

__global__ void __launch_bounds__(256) tc_gemm(
    const __nv_bfloat16* __restrict__ Ahi,
    const __nv_bfloat16* __restrict__ Alo,
    const __nv_bfloat16* __restrict__ Bhi_all,
    const __nv_bfloat16* __restrict__ Blo_all,
    float* __restrict__ proj_out,
    int mode)
{
    extern __shared__ char smc[];
    uint32_t sb = smem_u32(smc);
    const uint32_t sA[2] = {sb,           sb + 16384u};
    const uint32_t sB[2] = {sb + 32768u,  sb + 49152u};

    int tid = threadIdx.x, lane = tid & 31, wid = tid >> 5;
    int warpM = wid >> 2, warpN = wid & 3;            // 2 x 4
    int m0 = blockIdx.x * 128, n0 = blockIdx.y * 128, mat = blockIdx.z;

    const __nv_bfloat16* Bhi = Bhi_all + (size_t)mat * DIM * DIM;
    const __nv_bfloat16* Blo = Blo_all + (size_t)mat * DIM * DIM;

    float acc[4][4][4];
    #pragma unroll
    for (int i = 0; i < 4; i++)
        #pragma unroll
        for (int j = 0; j < 4; j++)
            #pragma unroll
            for (int k = 0; k < 4; k++) acc[i][j][k] = 0.f;

    auto issue_load = [&](int c) {
        int buf = c & 1;
        int seg = c / 6, kc = c - seg * 6, koff = kc * 64;
        const __nv_bfloat16* Ag = (seg == 2) ? Alo : Ahi;
        const __nv_bfloat16* Bg = (seg == 1) ? Blo : Bhi;
        #pragma unroll
        for (int it = 0; it < 4; it++) {
            int idx = it * 256 + tid;
            int row = idx >> 3, cc = idx & 7;
            uint32_t soff = (uint32_t)(row * 128 + ((cc ^ (row & 7)) << 4));
            cp_async16(sA[buf] + soff, Ag + (size_t)(m0 + row) * DIM + koff + cc * 8);
            cp_async16(sB[buf] + soff, Bg + (size_t)(n0 + row) * DIM + koff + cc * 8);
        }
        asm volatile("cp.async.commit_group;" ::: "memory");
    };

    issue_load(0);

    for (int c = 0; c < 18; c++) {
        if (c + 1 < 18) {
            issue_load(c + 1);
            asm volatile("cp.async.wait_group 1;" ::: "memory");
        } else {
            asm volatile("cp.async.wait_group 0;" ::: "memory");
        }
        __syncthreads();
        int buf = c & 1;
        #pragma unroll
        for (int ks = 0; ks < 4; ks++) {
            uint32_t afrag[4][4];
            #pragma unroll
            for (int mt = 0; mt < 4; mt++) {
                int r = warpM * 64 + mt * 16 + (lane & 15);
                int chunk = ((ks * 2 + (lane >> 4)) ^ (r & 7));
                ldsm_x4(afrag[mt], sA[buf] + (uint32_t)(r * 128 + chunk * 16));
            }
            uint32_t bfrag[2][4];
            #pragma unroll
            for (int bt = 0; bt < 2; bt++) {
                int r = warpN * 32 + bt * 16 + (lane & 15);
                int chunk = ((ks * 2 + (lane >> 4)) ^ (r & 7));
                ldsm_x4(bfrag[bt], sB[buf] + (uint32_t)(r * 128 + chunk * 16));
            }
            #pragma unroll
            for (int mt = 0; mt < 4; mt++)
                #pragma unroll
                for (int nt = 0; nt < 4; nt++) {
                    int bt = nt >> 1, j = nt & 1;
                    mma_bf16(acc[mt][nt], afrag[mt], bfrag[bt][j], bfrag[bt][j + 2]);
                }
        }
        __syncthreads();
    }

    int grow = m0 + warpM * 64 + (lane >> 2);
    int gcol = n0 + warpN * 32 + (lane & 3) * 2;
    #pragma unroll
    for (int mt = 0; mt < 4; mt++) {
        #pragma unroll
        for (int nt = 0; nt < 4; nt++) {
            int gm = grow + mt * 16;
            int gn = gcol + nt * 8;
            if (mode == 0) {
                __nv_bfloat16* Yh = (mat == 0) ? g_qhi : (mat == 1) ? g_khi : g_vhi;
                __nv_bfloat16* Yl = (mat == 0) ? g_qlo : (mat == 1) ? g_klo : g_vlo;
                int b = gm >> 10, nrow = gm & 1023;
                int h = gn >> 6,  dd = gn & 63;
                size_t base = ((size_t)(b * NH + h) << 16) + dd;
                uint32_t hh, ll;
                split_pair(acc[mt][nt][0], acc[mt][nt][1], hh, ll);
                *(uint32_t*)(Yh + base + ((size_t)nrow << 6)) = hh;
                *(uint32_t*)(Yl + base + ((size_t)nrow << 6)) = ll;
                split_pair(acc[mt][nt][2], acc[mt][nt][3], hh, ll);
                *(uint32_t*)(Yh + base + ((size_t)(nrow + 8) << 6)) = hh;
                *(uint32_t*)(Yl + base + ((size_t)(nrow + 8) << 6)) = ll;
            } else {
                *(float2*)(proj_out + (size_t)gm       * DIM + gn) =
                    make_float2(acc[mt][nt][0], acc[mt][nt][1]);
                *(float2*)(proj_out + (size_t)(gm + 8) * DIM + gn) =
                    make_float2(acc[mt][nt][2], acc[mt][nt][3]);
            }
        }
    }
}

// ---------------------------------------------------------------------------
// Tensor-core flash attention, split-bf16 (3-term) for S and PV.
// CTA: 128 q-rows of one (b,h). 8 warps; warp w owns rows [16w, 16w+16).
// Per k-tile (64 keys): S = (qh+ql)(kh+kl)^T (3 terms), +P, online softmax,
// prob split -> (ph+pl)(vh+vl) (3 terms). cp.async double-buffered K/V/P.
// ---------------------------------------------------------------------------
#define AT_STAGE 67584
#define AT_KHI 0
#define AT_KLO 8192
#define AT_VHI 16384
#define AT_VLO 24576
#define AT_P   32768
#define ATTN_SMEM (2*AT_STAGE)

__global__ void __launch_bounds__(256) attn_tc(const float* __restrict__ logit_lambda)
{
    extern __shared__ char smc[];
    uint32_t sb = smem_u32(smc);
    int tid = threadIdx.x, lane = tid & 31, w = tid >> 5;
    int qb0 = blockIdx.x * 128;
    int bh = blockIdx.y;
    int b_ = bh / NH, head = bh % NH;
    size_t base = (size_t)bh << 16;

    const __nv_bfloat16* qh = g_qhi + base;
    const __nv_bfloat16* ql = g_qlo + base;
    const __nv_bfloat16* kh = g_khi + base;
    const __nv_bfloat16* kl = g_klo + base;
    const __nv_bfloat16* vh = g_vhi + base;
    const __nv_bfloat16* vl = g_vlo + base;

    float lam   = 1.0f / (1.0f + __expf(-logit_lambda[0]));
    float scale = lam * 0.125f;

    // ---- preload Q fragments (stage0 first 16KB as staging) ----
    uint32_t qfh[4][4], qfl[4][4];
    #pragma unroll
    for (int pass = 0; pass < 2; pass++) {
        const __nv_bfloat16* src = pass ? ql : qh;
        #pragma unroll
        for (int it = 0; it < 4; it++) {
            int idx = it * 256 + tid;
            int row = idx >> 3, c = idx & 7;
            uint32_t soff = (uint32_t)(row * 128 + ((c ^ (row & 7)) << 4));
            cp_async16(sb + soff, src + (size_t)(qb0 + row) * 64 + c * 8);
        }
        asm volatile("cp.async.commit_group;\n\tcp.async.wait_group 0;" ::: "memory");
        __syncthreads();
        uint32_t (*dst)[4] = pass ? qfl : qfh;
        #pragma unroll
        for (int kk = 0; kk < 4; kk++) {
            int r = w * 16 + (lane & 15);
            int ch = ((kk * 2 + (lane >> 4)) ^ (r & 7));
            ldsm_x4(dst[kk], sb + (uint32_t)(r * 128 + ch * 16));
        }
        __syncthreads();
    }

    auto issue = [&](int kt) {
        uint32_t s0 = sb + (uint32_t)(kt & 1) * AT_STAGE;
        int k0 = kt * 64;
        #pragma unroll
        for (int it = 0; it < 2; it++) {
            int idx = it * 256 + tid;
            int row = idx >> 3, c = idx & 7;
            uint32_t soff = (uint32_t)(row * 128 + ((c ^ (row & 7)) << 4));
            size_t g = (size_t)(k0 + row) * 64 + c * 8;
            cp_async16(s0 + AT_KHI + soff, kh + g);
            cp_async16(s0 + AT_KLO + soff, kl + g);
            cp_async16(s0 + AT_VHI + soff, vh + g);
            cp_async16(s0 + AT_VLO + soff, vl + g);
        }
        #pragma unroll
        for (int it = 0; it < 8; it++) {
            int idx = it * 256 + tid;
            int row = idx >> 4, c = idx & 15;
            cp_async16(s0 + AT_P + (uint32_t)(row * 272 + c * 16),
                       g_pl + (size_t)(qb0 + row) * SEQ + k0 + c * 4);
        }
        asm volatile("cp.async.commit_group;" ::: "memory");
    };

    float m0 = -1e30f, m1 = -1e30f, l0 = 0.f, l1 = 0.f;
    float oacc[8][4];
    #pragma unroll
    for (int j = 0; j < 8; j++)
        #pragma unroll
        for (int i = 0; i < 4; i++) oacc[j][i] = 0.f;

    int g   = lane >> 2;
    int t2  = (lane & 3) * 2;

    issue(0); issue(1);

    for (int kt = 0; kt < 16; kt++) {
        if (kt < 15) asm volatile("cp.async.wait_group 1;" ::: "memory");
        else         asm volatile("cp.async.wait_group 0;" ::: "memory");
        __syncthreads();
        uint32_t s0 = sb + (uint32_t)(kt & 1) * AT_STAGE;
        const float* Pp = (const float*)(smc + (size_t)(kt & 1) * AT_STAGE + AT_P);

        // ---- S = 3-term QK^T ----
        float acc[8][4];
        #pragma unroll
        for (int j = 0; j < 8; j++)
            #pragma unroll
            for (int i = 0; i < 4; i++) acc[j][i] = 0.f;

        #pragma unroll
        for (int kk = 0; kk < 4; kk++) {
            uint32_t bf[4][4];
            #pragma unroll
            for (int bt = 0; bt < 4; bt++) {
                int r = bt * 16 + (lane & 15);
                int ch = ((kk * 2 + (lane >> 4)) ^ (r & 7));
                ldsm_x4(bf[bt], s0 + AT_KHI + (uint32_t)(r * 128 + ch * 16));
            }
            #pragma unroll
            for (int bt = 0; bt < 4; bt++)
                #pragma unroll
                for (int jj = 0; jj < 2; jj++) {
                    mma_bf16(acc[bt*2+jj], qfh[kk], bf[bt][jj], bf[bt][jj+2]);
                    mma_bf16(acc[bt*2+jj], qfl[kk], bf[bt][jj], bf[bt][jj+2]);
                }
            #pragma unroll
            for (int bt = 0; bt < 4; bt++) {
                int r = bt * 16 + (lane & 15);
                int ch = ((kk * 2 + (lane >> 4)) ^ (r & 7));
                ldsm_x4(bf[bt], s0 + AT_KLO + (uint32_t)(r * 128 + ch * 16));
            }
            #pragma unroll
            for (int bt = 0; bt < 4; bt++)
                #pragma unroll
                for (int jj = 0; jj < 2; jj++)
                    mma_bf16(acc[bt*2+jj], qfh[kk], bf[bt][jj], bf[bt][jj+2]);
        }

        // ---- + P, online softmax ----
        int prow0 = (w * 16 + g) * 68;
        int prow1 = prow0 + 8 * 68;
        float rmax0 = -1e30f, rmax1 = -1e30f;
        #pragma unroll
        for (int j = 0; j < 8; j++) {
            int col = t2 + 8 * j;
            acc[j][0] = acc[j][0] * scale + Pp[prow0 + col];
            acc[j][1] = acc[j][1] * scale + Pp[prow0 + col + 1];
            acc[j][2] = acc[j][2] * scale + Pp[prow1 + col];
            acc[j][3] = acc[j][3] * scale + Pp[prow1 + col + 1];
            rmax0 = fmaxf(rmax0, fmaxf(acc[j][0], acc[j][1]));
            rmax1 = fmaxf(rmax1, fmaxf(acc[j][2], acc[j][3]));
        }
        rmax0 = fmaxf(rmax0, __shfl_xor_sync(0xffffffffu, rmax0, 1));
        rmax0 = fmaxf(rmax0, __shfl_xor_sync(0xffffffffu, rmax0, 2));
        rmax1 = fmaxf(rmax1, __shfl_xor_sync(0xffffffffu, rmax1, 1));
        rmax1 = fmaxf(rmax1, __shfl_xor_sync(0xffffffffu, rmax1, 2));
        float nm0 = fmaxf(m0, rmax0), nm1 = fmaxf(m1, rmax1);
        float r0 = __expf(m0 - nm0),  r1 = __expf(m1 - nm1);
        float sum0 = 0.f, sum1 = 0.f;
        #pragma unroll
        for (int j = 0; j < 8; j++) {
            acc[j][0] = __expf(acc[j][0] - nm0);
            acc[j][1] = __expf(acc[j][1] - nm0);
            acc[j][2] = __expf(acc[j][2] - nm1);
            acc[j][3] = __expf(acc[j][3] - nm1);
            sum0 += acc[j][0] + acc[j][1];
            sum1 += acc[j][2] + acc[j][3];
        }
        sum0 += __shfl_xor_sync(0xffffffffu, sum0, 1);
        sum0 += __shfl_xor_sync(0xffffffffu, sum0, 2);
        sum1 += __shfl_xor_sync(0xffffffffu, sum1, 1);
        sum1 += __shfl_xor_sync(0xffffffffu, sum1, 2);
        l0 = l0 * r0 + sum0;  l1 = l1 * r1 + sum1;
        m0 = nm0;             m1 = nm1;
        #pragma unroll
        for (int j = 0; j < 8; j++) {
            oacc[j][0] *= r0; oacc[j][1] *= r0;
            oacc[j][2] *= r1; oacc[j][3] *= r1;
        }

        // ---- O += (ph+pl) (vh+vl) : 3 terms ----
        #pragma unroll
        for (int kk = 0; kk < 4; kk++) {
            uint32_t ah[4], al[4];
            split_pair(acc[2*kk][0],   acc[2*kk][1],   ah[0], al[0]);
            split_pair(acc[2*kk][2],   acc[2*kk][3],   ah[1], al[1]);
            split_pair(acc[2*kk+1][0], acc[2*kk+1][1], ah[2], al[2]);
            split_pair(acc[2*kk+1][2], acc[2*kk+1][3], ah[3], al[3]);

            uint32_t bv[4][4];
            #pragma unroll
            for (int ntp = 0; ntp < 4; ntp++) {
                int r = kk * 16 + (lane & 15);
                int ch = ((ntp * 2 + (lane >> 4)) ^ (r & 7));
                ldsm_x4_t(bv[ntp], s0 + AT_VHI + (uint32_t)(r * 128 + ch * 16));
            }
            #pragma unroll
            for (int ntp = 0; ntp < 4; ntp++) {
                mma_bf16(oacc[2*ntp],   ah, bv[ntp][0], bv[ntp][1]);
                mma_bf16(oacc[2*ntp+1], ah, bv[ntp][2], bv[ntp][3]);
                mma_bf16(oacc[2*ntp],   al, bv[ntp][0], bv[ntp][1]);
                mma_bf16(oacc[2*ntp+1], al, bv[ntp][2], bv[ntp][3]);
            }
            #pragma unroll
            for (int ntp = 0; ntp < 4; ntp++) {
                int r = kk * 16 + (lane & 15);
                int ch = ((ntp * 2 + (lane >> 4)) ^ (r & 7));
                ldsm_x4_t(bv[ntp], s0 + AT_VLO + (uint32_t)(r * 128 + ch * 16));
            }
            #pragma unroll
            for (int ntp = 0; ntp < 4; ntp++) {
                mma_bf16(oacc[2*ntp],   ah, bv[ntp][0], bv[ntp][1]);
                mma_bf16(oacc[2*ntp+1], ah, bv[ntp][2], bv[ntp][3]);
            }
        }

        __syncthreads();
        if (kt + 2 < 16) issue(kt + 2);
    }

    // ---- epilogue: O/l -> bf16 hi/lo into g_aohi/g_aolo ----
    float i0 = 1.0f / l0, i1 = 1.0f / l1;
    int row0 = b_ * SEQ + qb0 + w * 16 + g;
    size_t ob0 = (size_t)row0 * DIM + head * 64;
    size_t ob1 = ob0 + (size_t)8 * DIM;
    #pragma unroll
    for (int j = 0; j < 8; j++) {
        int col = t2 + 8 * j;
        uint32_t hh, ll;
        split_pair(oacc[j][0] * i0, oacc[j][1] * i0, hh, ll);
        *(uint32_t*)(g_aohi + ob0 + col) = hh;
        *(uint32_t*)(g_aolo + ob0 + col) = ll;
        split_pair(oacc[j][2] * i1, oacc[j][3] * i1, hh, ll);
        *(uint32_t*)(g_aohi + ob1 + col) = hh;
        *(uint32_t*)(g_aolo + ob1 + col) = ll;
    }
}

// ---------------------------------------------------------------------------
extern "C" void kernel_launch(void* const* d_in, const int* in_sizes, int n_in,
                              void* d_out, int out_size)
{
    const float* x  = (const float*)d_in[0];
    const float* Wq = (const float*)d_in[1];
    const float* Wk = (const float*)d_in[2];
    const float* Wv = (const float*)d_in[3];
    const float* Wp = (const float*)d_in[4];
    const float* ll = (const float*)d_in[5];
    const float* ls = (const float*)d_in[6];
    float* out = (float*)d_out;

    cudaFuncSetAttribute(tc_gemm,
                         cudaFuncAttributeMaxDynamicSharedMemorySize, GEMM_SMEM);
    cudaFuncSetAttribute(attn_tc,
                         cudaFuncAttributeMaxDynamicSharedMemorySize, ATTN_SMEM);

    __nv_bfloat16 *xhi, *xlo, *aohi, *aolo, *whi, *wlo;
    cudaGetSymbolAddress((void**)&xhi,  g_xhi);
    cudaGetSymbolAddress((void**)&xlo,  g_xlo);
    cudaGetSymbolAddress((void**)&aohi, g_aohi);
    cudaGetSymbolAddress((void**)&aolo, g_aolo);
    cudaGetSymbolAddress((void**)&whi,  g_whi);
    cudaGetSymbolAddress((void**)&wlo,  g_wlo);

    pos_kernel<<<SEQ, 256>>>(ll, ls);

    convert_split<<<(MTOT*DIM + 255)/256, 256>>>(x, xhi, xlo, MTOT*DIM);
    convert_split<<<(DIM*DIM + 255)/256, 256>>>(Wq, whi + 0*DIM*DIM, wlo + 0*DIM*DIM, DIM*DIM);
    convert_split<<<(DIM*DIM + 255)/256, 256>>>(Wk, whi + 1*DIM*DIM, wlo + 1*DIM*DIM, DIM*DIM);
    convert_split<<<(DIM*DIM + 255)/256, 256>>>(Wv, whi + 2*DIM*DIM, wlo + 2*DIM*DIM, DIM*DIM);
    convert_split<<<(DIM*DIM + 255)/256, 256>>>(Wp, whi + 3*DIM*DIM, wlo + 3*DIM*DIM, DIM*DIM);

    tc_gemm<<<dim3(64, 3, 3), 256, GEMM_SMEM>>>(xhi, xlo, whi, wlo, nullptr, 0);

    attn_tc<<<dim3(SEQ/128, BATCH*NH), 256, ATTN_SMEM>>>(ll);

    tc_gemm<<<dim3(64, 3, 1), 256, GEMM_SMEM>>>(aohi, aolo,
                                                whi + 3*DIM*DIM, wlo + 3*DIM*DIM,
                                                out, 1);
}